// round 2
// baseline (speedup 1.0000x reference)
#include <cuda_runtime.h>
#include <math.h>

// Problem constants
#define BATCH   4
#define NSEQ    2048
#define DMODEL  1024
#define NH      16
#define DK      64
#define MROWS   (BATCH * NSEQ)   // 8192

// Scratch (allocation-free rule: __device__ globals)
__device__ float g_Q[BATCH * NH * NSEQ * DK];   // (B,H,N,DK)
__device__ float g_K[BATCH * NH * NSEQ * DK];
__device__ float g_V[BATCH * NH * NSEQ * DK];
__device__ float g_O[BATCH * NSEQ * DMODEL];    // (B,N,D) concat-heads

// ---------------------------------------------------------------------------
// Fast exp: e^x via 2^(x*log2e), rint split + degree-5 poly on [-0.5,0.5].
// Max rel err ~2.4e-6. Avoids MUFU EX2 throughput wall (268M exps needed).
// ---------------------------------------------------------------------------
__device__ __forceinline__ float fexp(float x) {
    float y = x * 1.4426950408889634f;
    y = fmaxf(fminf(y, 126.0f), -126.0f);
    float n = rintf(y);
    float f = y - n;
    float p = 1.33335581e-3f;
    p = fmaf(p, f, 9.61812911e-3f);
    p = fmaf(p, f, 5.55041087e-2f);
    p = fmaf(p, f, 2.40226507e-1f);
    p = fmaf(p, f, 6.93147181e-1f);
    p = fmaf(p, f, 1.0f);
    return __int_as_float((((int)n) + 127) << 23) * p;
}

// ---------------------------------------------------------------------------
// GEMM: out = X(8192x1024) @ W(1024x1024) + bias
// BM=128, BN=128, BK=16, 256 threads, 8x8 per thread.
// SPLIT: write in (B,H,N,DK) head-split layout; else plain (M,1024).
// ---------------------------------------------------------------------------
template <bool SPLIT>
__global__ void __launch_bounds__(256) gemm_bias(
    const float* __restrict__ X, const float* __restrict__ W,
    const float* __restrict__ bias, float* __restrict__ out)
{
    __shared__ float As[16][128];   // transposed A tile: As[k][m]
    __shared__ float Bs[16][128];   // Bs[k][n]

    const int tid = threadIdx.x;
    const int tx = tid & 15, ty = tid >> 4;
    const int m0 = blockIdx.y * 128;
    const int n0 = blockIdx.x * 128;

    float acc[8][8];
#pragma unroll
    for (int i = 0; i < 8; i++)
#pragma unroll
        for (int j = 0; j < 8; j++) acc[i][j] = 0.0f;

    for (int k0 = 0; k0 < DMODEL; k0 += 16) {
        // Load A tile (128x16), store transposed
#pragma unroll
        for (int q = 0; q < 2; q++) {
            int f = tid + q * 256;           // float4 index 0..511
            int row = f >> 2;                // 0..127
            int kc  = (f & 3) << 2;          // 0,4,8,12
            float4 v = *(const float4*)(X + (size_t)(m0 + row) * DMODEL + k0 + kc);
            As[kc + 0][row] = v.x;
            As[kc + 1][row] = v.y;
            As[kc + 2][row] = v.z;
            As[kc + 3][row] = v.w;
        }
        // Load B tile (16x128)
#pragma unroll
        for (int q = 0; q < 2; q++) {
            int f = tid + q * 256;
            int row = f >> 5;                // 0..15
            int c   = (f & 31) << 2;         // 0..124
            *(float4*)&Bs[row][c] =
                *(const float4*)(W + (size_t)(k0 + row) * DMODEL + n0 + c);
        }
        __syncthreads();

#pragma unroll
        for (int kk = 0; kk < 16; kk++) {
            float a[8], b[8];
            *(float4*)&a[0] = *(float4*)&As[kk][ty * 8];
            *(float4*)&a[4] = *(float4*)&As[kk][ty * 8 + 4];
            *(float4*)&b[0] = *(float4*)&Bs[kk][tx * 8];
            *(float4*)&b[4] = *(float4*)&Bs[kk][tx * 8 + 4];
#pragma unroll
            for (int i = 0; i < 8; i++)
#pragma unroll
                for (int j = 0; j < 8; j++)
                    acc[i][j] = fmaf(a[i], b[j], acc[i][j]);
        }
        __syncthreads();
    }

    // Epilogue
#pragma unroll
    for (int i = 0; i < 8; i++) {
        int m = m0 + ty * 8 + i;
        int b = m >> 11;          // m / 2048
        int n = m & 2047;
#pragma unroll
        for (int j = 0; j < 8; j += 4) {
            int col = n0 + tx * 8 + j;
            float4 r;
            r.x = acc[i][j + 0] + bias[col + 0];
            r.y = acc[i][j + 1] + bias[col + 1];
            r.z = acc[i][j + 2] + bias[col + 2];
            r.w = acc[i][j + 3] + bias[col + 3];
            if (SPLIT) {
                int h  = col >> 6;     // col / 64
                int dk = col & 63;
                *(float4*)&out[(((size_t)((b << 4) + h) * NSEQ + n) * DK) + dk] = r;
            } else {
                *(float4*)&out[(size_t)m * DMODEL + col] = r;
            }
        }
    }
}

// ---------------------------------------------------------------------------
// Fused attention: per block = one (b,h) and 64 query rows; stream 64-key
// tiles with online softmax. 256 threads, thread (tx,ty) owns a 4x4 microtile.
// Smem: Qs/Ks transposed+swizzled [d][r], Vs plain [k][d], Ps swizzled [c][r].
// Swizzle: phys(row, col) = row*64 + ((((col>>2) ^ ((row>>2)&15)) << 2) | (col&3))
// -> conflict-free LDS.128 in both GEMM loops, 2-way on transpose stores.
// ---------------------------------------------------------------------------
#define SWZ(row, col) ((row) * 64 + (((((col) >> 2) ^ (((row) >> 2) & 15)) << 2) | ((col) & 3)))

__global__ void __launch_bounds__(256) attn_kernel(
    const int* __restrict__ mask, float* __restrict__ gO)
{
    extern __shared__ float sm[];
    float* Qs = sm;            // 4096 floats
    float* Ks = sm + 4096;
    float* Vs = sm + 8192;
    float* Ps = sm + 12288;

    const int bh = blockIdx.x;           // 0..63
    const int qt = blockIdx.y;           // 0..31
    const int b  = bh >> 4;
    const int h  = bh & 15;
    const int tid = threadIdx.x;
    const int tx = tid & 15, ty = tid >> 4;

    const float* Qg = g_Q + ((size_t)bh * NSEQ + qt * 64) * DK;
    const float* Kg = g_K + (size_t)bh * NSEQ * DK;
    const float* Vg = g_V + (size_t)bh * NSEQ * DK;
    const int*   Mg = mask + ((size_t)b * NSEQ + qt * 64) * NSEQ;

    // Load Q tile, transposed + swizzled
#pragma unroll
    for (int q = 0; q < 4; q++) {
        int f = tid + q * 256;     // float4 idx 0..1023
        int r  = f >> 4;           // 0..63
        int d4 = f & 15;
        float4 v = *(const float4*)(Qg + r * DK + d4 * 4);
        int d = d4 * 4;
        Qs[SWZ(d + 0, r)] = v.x;
        Qs[SWZ(d + 1, r)] = v.y;
        Qs[SWZ(d + 2, r)] = v.z;
        Qs[SWZ(d + 3, r)] = v.w;
    }

    float m_i[4], l_i[4], o_acc[4][4];
#pragma unroll
    for (int i = 0; i < 4; i++) {
        m_i[i] = -1e30f;
        l_i[i] = 0.0f;
#pragma unroll
        for (int j = 0; j < 4; j++) o_acc[i][j] = 0.0f;
    }

    for (int kt = 0; kt < NSEQ; kt += 64) {
        __syncthreads();   // previous PV done before overwriting Ks/Vs
        // Load K (transposed+swizzled) and V (plain) tiles
#pragma unroll
        for (int q = 0; q < 4; q++) {
            int f = tid + q * 256;
            int r  = f >> 4;
            int d4 = f & 15;
            float4 kv = *(const float4*)(Kg + (size_t)(kt + r) * DK + d4 * 4);
            int d = d4 * 4;
            Ks[SWZ(d + 0, r)] = kv.x;
            Ks[SWZ(d + 1, r)] = kv.y;
            Ks[SWZ(d + 2, r)] = kv.z;
            Ks[SWZ(d + 3, r)] = kv.w;
            *(float4*)&Vs[r * 64 + d4 * 4] =
                *(const float4*)(Vg + (size_t)(kt + r) * DK + d4 * 4);
        }
        __syncthreads();

        // S = Q K^T  (4x4 per thread)
        float s[4][4];
#pragma unroll
        for (int i = 0; i < 4; i++)
#pragma unroll
            for (int j = 0; j < 4; j++) s[i][j] = 0.0f;

#pragma unroll
        for (int d = 0; d < 64; d++) {
            int sw = (d >> 2) & 15;
            float4 a = *(float4*)&Qs[d * 64 + ((ty ^ sw) << 2)];
            float4 kb = *(float4*)&Ks[d * 64 + ((tx ^ sw) << 2)];
            float av[4] = {a.x, a.y, a.z, a.w};
            float bv[4] = {kb.x, kb.y, kb.z, kb.w};
#pragma unroll
            for (int i = 0; i < 4; i++)
#pragma unroll
                for (int j = 0; j < 4; j++)
                    s[i][j] = fmaf(av[i], bv[j], s[i][j]);
        }

        // Scale + mask (replace with NEG where mask==0, like the reference)
#pragma unroll
        for (int i = 0; i < 4; i++) {
            const int4 mv = *(const int4*)(Mg + (size_t)(ty * 4 + i) * NSEQ + kt + tx * 4);
            s[i][0] = (mv.x == 0) ? -1e11f : s[i][0] * 0.125f;
            s[i][1] = (mv.y == 0) ? -1e11f : s[i][1] * 0.125f;
            s[i][2] = (mv.z == 0) ? -1e11f : s[i][2] * 0.125f;
            s[i][3] = (mv.w == 0) ? -1e11f : s[i][3] * 0.125f;
        }

        // Online softmax per row; row = 16 lanes with same ty (xor<=8 stays in group)
        float corr_i[4];
#pragma unroll
        for (int i = 0; i < 4; i++) {
            float mx = fmaxf(fmaxf(s[i][0], s[i][1]), fmaxf(s[i][2], s[i][3]));
#pragma unroll
            for (int off = 1; off < 16; off <<= 1)
                mx = fmaxf(mx, __shfl_xor_sync(0xffffffffu, mx, off));
            float mnew = fmaxf(m_i[i], mx);
            float corr = fexp(m_i[i] - mnew);
            m_i[i] = mnew;
            float rs = 0.0f;
#pragma unroll
            for (int j = 0; j < 4; j++) {
                float p = fexp(s[i][j] - mnew);
                s[i][j] = p;
                rs += p;
            }
#pragma unroll
            for (int off = 1; off < 16; off <<= 1)
                rs += __shfl_xor_sync(0xffffffffu, rs, off);
            l_i[i] = l_i[i] * corr + rs;
            corr_i[i] = corr;
            // write P transposed (c, r) swizzled
            int r = ty * 4 + i;
#pragma unroll
            for (int j = 0; j < 4; j++)
                Ps[SWZ(tx * 4 + j, r)] = s[i][j];
        }
        __syncthreads();

        // O = O*corr + P @ V
#pragma unroll
        for (int i = 0; i < 4; i++)
#pragma unroll
            for (int j = 0; j < 4; j++) o_acc[i][j] *= corr_i[i];

#pragma unroll
        for (int k = 0; k < 64; k++) {
            int sw = (k >> 2) & 15;
            float4 p = *(float4*)&Ps[k * 64 + ((ty ^ sw) << 2)];
            float4 v = *(float4*)&Vs[k * 64 + tx * 4];
            float pv[4] = {p.x, p.y, p.z, p.w};
            float vv[4] = {v.x, v.y, v.z, v.w};
#pragma unroll
            for (int i = 0; i < 4; i++)
#pragma unroll
                for (int j = 0; j < 4; j++)
                    o_acc[i][j] = fmaf(pv[i], vv[j], o_acc[i][j]);
        }
    }

    // Normalize + write concat-heads layout (B,N,DMODEL)
#pragma unroll
    for (int i = 0; i < 4; i++) {
        int qrow = qt * 64 + ty * 4 + i;
        float inv = 1.0f / l_i[i];
        float4 r;
        r.x = o_acc[i][0] * inv;
        r.y = o_acc[i][1] * inv;
        r.z = o_acc[i][2] * inv;
        r.w = o_acc[i][3] * inv;
        *(float4*)&gO[((size_t)b * NSEQ + qrow) * DMODEL + h * DK + tx * 4] = r;
    }
}

// ---------------------------------------------------------------------------
// Launch
// ---------------------------------------------------------------------------
extern "C" void kernel_launch(void* const* d_in, const int* in_sizes, int n_in,
                              void* d_out, int out_size)
{
    const float* query = (const float*)d_in[0];
    const float* key   = (const float*)d_in[1];
    const float* value = (const float*)d_in[2];
    const int*   mask  = (const int*)  d_in[3];
    const float* Wq    = (const float*)d_in[4];
    const float* bq    = (const float*)d_in[5];
    const float* Wk    = (const float*)d_in[6];
    const float* bk    = (const float*)d_in[7];
    const float* Wv    = (const float*)d_in[8];
    const float* bv    = (const float*)d_in[9];
    const float* Wo    = (const float*)d_in[10];
    const float* bo    = (const float*)d_in[11];

    float *Qp, *Kp, *Vp, *Op;
    cudaGetSymbolAddress((void**)&Qp, g_Q);
    cudaGetSymbolAddress((void**)&Kp, g_K);
    cudaGetSymbolAddress((void**)&Vp, g_V);
    cudaGetSymbolAddress((void**)&Op, g_O);

    cudaFuncSetAttribute(attn_kernel,
                         cudaFuncAttributeMaxDynamicSharedMemorySize, 65536);

    dim3 gp(DMODEL / 128, MROWS / 128);   // (8, 64)
    gemm_bias<true><<<gp, 256>>>(query, Wq, bq, Qp);
    gemm_bias<true><<<gp, 256>>>(key,   Wk, bk, Kp);
    gemm_bias<true><<<gp, 256>>>(value, Wv, bv, Vp);

    attn_kernel<<<dim3(BATCH * NH, NSEQ / 64), 256, 65536>>>(mask, Op);

    gemm_bias<false><<<gp, 256>>>(Op, Wo, bo, (float*)d_out);
}

// round 4
// speedup vs baseline: 1.4056x; 1.4056x over previous
#include <cuda_runtime.h>
#include <cuda_fp16.h>
#include <math.h>
#include <stdint.h>

// Problem constants
#define BATCH   4
#define NSEQ    2048
#define DMODEL  1024
#define NH      16
#define DK      64
#define MROWS   (BATCH * NSEQ)   // 8192

// Scratch (allocation-free rule: __device__ globals)
__device__ float g_Q[BATCH * NH * NSEQ * DK];   // (B,H,N,DK)
__device__ float g_K[BATCH * NH * NSEQ * DK];
__device__ float g_V[BATCH * NH * NSEQ * DK];
__device__ float g_O[BATCH * NSEQ * DMODEL];    // (B,N,D) concat-heads

// ---------------------------------------------------------------------------
// mma.sync helpers (sm_80+ ISA, works on base sm_100 target)
// ---------------------------------------------------------------------------
__device__ __forceinline__ uint32_t smem_u32(const void* p) {
    uint32_t a;
    asm("{ .reg .u64 t; cvta.to.shared.u64 t, %1; cvt.u32.u64 %0, t; }"
        : "=r"(a) : "l"(p));
    return a;
}

__device__ __forceinline__ void ldmx4(uint32_t* r, uint32_t addr) {
    asm volatile("ldmatrix.sync.aligned.m8n8.x4.shared.b16 {%0,%1,%2,%3}, [%4];"
                 : "=r"(r[0]), "=r"(r[1]), "=r"(r[2]), "=r"(r[3]) : "r"(addr));
}
__device__ __forceinline__ void ldmx4t(uint32_t* r, uint32_t addr) {
    asm volatile("ldmatrix.sync.aligned.m8n8.x4.trans.shared.b16 {%0,%1,%2,%3}, [%4];"
                 : "=r"(r[0]), "=r"(r[1]), "=r"(r[2]), "=r"(r[3]) : "r"(addr));
}
__device__ __forceinline__ void mma16816(float* d, const uint32_t* a,
                                         uint32_t b0, uint32_t b1) {
    asm volatile(
        "mma.sync.aligned.m16n8k16.row.col.f32.f16.f16.f32 "
        "{%0,%1,%2,%3}, {%4,%5,%6,%7}, {%8,%9}, {%0,%1,%2,%3};"
        : "+f"(d[0]), "+f"(d[1]), "+f"(d[2]), "+f"(d[3])
        : "r"(a[0]), "r"(a[1]), "r"(a[2]), "r"(a[3]), "r"(b0), "r"(b1));
}

// Split fp32x4 into fp16 hi + fp16 residual, packed as half2 words
__device__ __forceinline__ void split4(float4 v, uint2& hi, uint2& lo) {
    float f[4] = {v.x, v.y, v.z, v.w};
    __half h[4], l[4];
#pragma unroll
    for (int i = 0; i < 4; i++) {
        h[i] = __float2half_rn(f[i]);
        l[i] = __float2half_rn(f[i] - __half2float(h[i]));
    }
    hi.x = (uint32_t)__half_as_ushort(h[0]) | ((uint32_t)__half_as_ushort(h[1]) << 16);
    hi.y = (uint32_t)__half_as_ushort(h[2]) | ((uint32_t)__half_as_ushort(h[3]) << 16);
    lo.x = (uint32_t)__half_as_ushort(l[0]) | ((uint32_t)__half_as_ushort(l[1]) << 16);
    lo.y = (uint32_t)__half_as_ushort(l[2]) | ((uint32_t)__half_as_ushort(l[3]) << 16);
}

// ---------------------------------------------------------------------------
// Tensor-core GEMM: out = X(8192x1024) @ W(1024x1024) + bias
// CTA 128x128, BK=32, 8 warps (4 m x 2 n), warp tile 32x64.
// Split-fp16 3-MMA: D += Ah*Bh + Ah*Bl + Al*Bh (fp32 accum).
// A smem row-major stride 40 halves (conflict-free ldmatrix);
// B smem native (k,n) stride 136 halves, ldmatrix.x4.trans.
// ---------------------------------------------------------------------------
#define SA 40
#define SB 136

template <bool SPLIT>
__global__ void __launch_bounds__(256) gemm_mma(
    const float* __restrict__ X, const float* __restrict__ W,
    const float* __restrict__ bias, float* __restrict__ out)
{
    __shared__ __half Ah[128 * SA], Al[128 * SA];
    __shared__ __half Bh[32 * SB],  Bl[32 * SB];

    const int tid = threadIdx.x;
    const int wid = tid >> 5;
    const int lane = tid & 31;
    const int wm = wid & 3;          // warp row: 32 rows each
    const int wn = wid >> 2;         // warp col: 64 cols each
    const int m0 = blockIdx.y * 128;
    const int n0 = blockIdx.x * 128;

    const uint32_t sAh = smem_u32(Ah), sAl = smem_u32(Al);
    const uint32_t sBh = smem_u32(Bh), sBl = smem_u32(Bl);

    float acc[2][8][4];
#pragma unroll
    for (int i = 0; i < 2; i++)
#pragma unroll
        for (int j = 0; j < 8; j++)
#pragma unroll
            for (int q = 0; q < 4; q++) acc[i][j][q] = 0.0f;

    // ldmatrix per-lane base offsets (halves)
    const int lrow = lane & 15;
    const int lcol = (lane >> 4) << 3;

    for (int c = 0; c < 32; ++c) {
        __syncthreads();
        // A: 128 rows x 32 k fp32 -> hi/lo fp16
        const float* Xc = X + (size_t)m0 * DMODEL + c * 32;
#pragma unroll
        for (int p = 0; p < 4; ++p) {
            int f = tid + p * 256;
            int r = f >> 3;          // 0..127
            int q = f & 7;           // float4 index in row
            float4 v = *(const float4*)(Xc + (size_t)r * DMODEL + q * 4);
            uint2 hi, lo;
            split4(v, hi, lo);
            *(uint2*)&Ah[r * SA + q * 4] = hi;
            *(uint2*)&Al[r * SA + q * 4] = lo;
        }
        // B: 32 k-rows x 128 n fp32 -> hi/lo fp16 (native layout)
        const float* Wc = W + (size_t)(c * 32) * DMODEL + n0;
#pragma unroll
        for (int p = 0; p < 4; ++p) {
            int f = tid + p * 256;
            int k = f >> 5;          // 0..31
            int q = f & 31;          // float4 index in row of 128
            float4 v = *(const float4*)(Wc + (size_t)k * DMODEL + q * 4);
            uint2 hi, lo;
            split4(v, hi, lo);
            *(uint2*)&Bh[k * SB + q * 4] = hi;
            *(uint2*)&Bl[k * SB + q * 4] = lo;
        }
        __syncthreads();

#pragma unroll
        for (int ks = 0; ks < 2; ++ks) {
            // A fragments: 2 m-tiles, hi+lo
            uint32_t ah[2][4], al[2][4];
#pragma unroll
            for (int i = 0; i < 2; i++) {
                uint32_t off = (uint32_t)((wm * 32 + i * 16 + lrow) * SA +
                                          ks * 16 + lcol) * 2;
                ldmx4(ah[i], sAh + off);
                ldmx4(al[i], sAl + off);
            }
#pragma unroll
            for (int j2 = 0; j2 < 4; ++j2) {   // 16-col chunks of warp's 64
                uint32_t bh[4], bl[4];
                uint32_t off = (uint32_t)((ks * 16 + lrow) * SB +
                                          wn * 64 + j2 * 16 + lcol) * 2;
                ldmx4t(bh, sBh + off);
                ldmx4t(bl, sBl + off);
#pragma unroll
                for (int i = 0; i < 2; i++) {
                    mma16816(acc[i][2 * j2],     ah[i], bh[0], bh[1]);
                    mma16816(acc[i][2 * j2 + 1], ah[i], bh[2], bh[3]);
                    mma16816(acc[i][2 * j2],     ah[i], bl[0], bl[1]);
                    mma16816(acc[i][2 * j2 + 1], ah[i], bl[2], bl[3]);
                    mma16816(acc[i][2 * j2],     al[i], bh[0], bh[1]);
                    mma16816(acc[i][2 * j2 + 1], al[i], bh[2], bh[3]);
                }
            }
        }
    }

    // Epilogue: fragment d: rows (lane>>2, +8), cols (lane&3)*2 +{0,1}
#pragma unroll
    for (int i = 0; i < 2; i++) {
#pragma unroll
        for (int j = 0; j < 8; j++) {
            int col = n0 + wn * 64 + j * 8 + (lane & 3) * 2;
            float b0 = bias[col], b1 = bias[col + 1];
#pragma unroll
            for (int half = 0; half < 2; half++) {
                int m = m0 + wm * 32 + i * 16 + (lane >> 2) + half * 8;
                float2 r;
                r.x = acc[i][j][half * 2 + 0] + b0;
                r.y = acc[i][j][half * 2 + 1] + b1;
                if (SPLIT) {
                    int bb = m >> 11;
                    int n  = m & 2047;
                    int h  = col >> 6;
                    int dk = col & 63;
                    *(float2*)&out[(((size_t)((bb << 4) + h) * NSEQ + n) * DK) + dk] = r;
                } else {
                    *(float2*)&out[(size_t)m * DMODEL + col] = r;
                }
            }
        }
    }
}

// ---------------------------------------------------------------------------
// Fast exp: e^x via 2^(x*log2e), rint split + degree-5 poly on [-0.5,0.5].
// ---------------------------------------------------------------------------
__device__ __forceinline__ float fexp(float x) {
    float y = x * 1.4426950408889634f;
    y = fmaxf(fminf(y, 126.0f), -126.0f);
    float n = rintf(y);
    float f = y - n;
    float p = 1.33335581e-3f;
    p = fmaf(p, f, 9.61812911e-3f);
    p = fmaf(p, f, 5.55041087e-2f);
    p = fmaf(p, f, 2.40226507e-1f);
    p = fmaf(p, f, 6.93147181e-1f);
    p = fmaf(p, f, 1.0f);
    return __int_as_float((((int)n) + 127) << 23) * p;
}

// ---------------------------------------------------------------------------
// Fused fp32 flash attention (validated Round-2 kernel, unchanged)
// ---------------------------------------------------------------------------
#define SWZ(row, col) ((row) * 64 + (((((col) >> 2) ^ (((row) >> 2) & 15)) << 2) | ((col) & 3)))

__global__ void __launch_bounds__(256) attn_kernel(
    const int* __restrict__ mask, float* __restrict__ gO)
{
    extern __shared__ float sm[];
    float* Qs = sm;
    float* Ks = sm + 4096;
    float* Vs = sm + 8192;
    float* Ps = sm + 12288;

    const int bh = blockIdx.x;
    const int qt = blockIdx.y;
    const int b  = bh >> 4;
    const int h  = bh & 15;
    const int tid = threadIdx.x;
    const int tx = tid & 15, ty = tid >> 4;

    const float* Qg = g_Q + ((size_t)bh * NSEQ + qt * 64) * DK;
    const float* Kg = g_K + (size_t)bh * NSEQ * DK;
    const float* Vg = g_V + (size_t)bh * NSEQ * DK;
    const int*   Mg = mask + ((size_t)b * NSEQ + qt * 64) * NSEQ;

#pragma unroll
    for (int q = 0; q < 4; q++) {
        int f = tid + q * 256;
        int r  = f >> 4;
        int d4 = f & 15;
        float4 v = *(const float4*)(Qg + r * DK + d4 * 4);
        int d = d4 * 4;
        Qs[SWZ(d + 0, r)] = v.x;
        Qs[SWZ(d + 1, r)] = v.y;
        Qs[SWZ(d + 2, r)] = v.z;
        Qs[SWZ(d + 3, r)] = v.w;
    }

    float m_i[4], l_i[4], o_acc[4][4];
#pragma unroll
    for (int i = 0; i < 4; i++) {
        m_i[i] = -1e30f;
        l_i[i] = 0.0f;
#pragma unroll
        for (int j = 0; j < 4; j++) o_acc[i][j] = 0.0f;
    }

    for (int kt = 0; kt < NSEQ; kt += 64) {
        __syncthreads();
#pragma unroll
        for (int q = 0; q < 4; q++) {
            int f = tid + q * 256;
            int r  = f >> 4;
            int d4 = f & 15;
            float4 kv = *(const float4*)(Kg + (size_t)(kt + r) * DK + d4 * 4);
            int d = d4 * 4;
            Ks[SWZ(d + 0, r)] = kv.x;
            Ks[SWZ(d + 1, r)] = kv.y;
            Ks[SWZ(d + 2, r)] = kv.z;
            Ks[SWZ(d + 3, r)] = kv.w;
            *(float4*)&Vs[r * 64 + d4 * 4] =
                *(const float4*)(Vg + (size_t)(kt + r) * DK + d4 * 4);
        }
        __syncthreads();

        float s[4][4];
#pragma unroll
        for (int i = 0; i < 4; i++)
#pragma unroll
            for (int j = 0; j < 4; j++) s[i][j] = 0.0f;

#pragma unroll
        for (int d = 0; d < 64; d++) {
            int sw = (d >> 2) & 15;
            float4 a = *(float4*)&Qs[d * 64 + ((ty ^ sw) << 2)];
            float4 kb = *(float4*)&Ks[d * 64 + ((tx ^ sw) << 2)];
            float av[4] = {a.x, a.y, a.z, a.w};
            float bv[4] = {kb.x, kb.y, kb.z, kb.w};
#pragma unroll
            for (int i = 0; i < 4; i++)
#pragma unroll
                for (int j = 0; j < 4; j++)
                    s[i][j] = fmaf(av[i], bv[j], s[i][j]);
        }

#pragma unroll
        for (int i = 0; i < 4; i++) {
            const int4 mv = *(const int4*)(Mg + (size_t)(ty * 4 + i) * NSEQ + kt + tx * 4);
            s[i][0] = (mv.x == 0) ? -1e11f : s[i][0] * 0.125f;
            s[i][1] = (mv.y == 0) ? -1e11f : s[i][1] * 0.125f;
            s[i][2] = (mv.z == 0) ? -1e11f : s[i][2] * 0.125f;
            s[i][3] = (mv.w == 0) ? -1e11f : s[i][3] * 0.125f;
        }

        float corr_i[4];
#pragma unroll
        for (int i = 0; i < 4; i++) {
            float mx = fmaxf(fmaxf(s[i][0], s[i][1]), fmaxf(s[i][2], s[i][3]));
#pragma unroll
            for (int off = 1; off < 16; off <<= 1)
                mx = fmaxf(mx, __shfl_xor_sync(0xffffffffu, mx, off));
            float mnew = fmaxf(m_i[i], mx);
            float corr = fexp(m_i[i] - mnew);
            m_i[i] = mnew;
            float rs = 0.0f;
#pragma unroll
            for (int j = 0; j < 4; j++) {
                float p = fexp(s[i][j] - mnew);
                s[i][j] = p;
                rs += p;
            }
#pragma unroll
            for (int off = 1; off < 16; off <<= 1)
                rs += __shfl_xor_sync(0xffffffffu, rs, off);
            l_i[i] = l_i[i] * corr + rs;
            corr_i[i] = corr;
            int r = ty * 4 + i;
#pragma unroll
            for (int j = 0; j < 4; j++)
                Ps[SWZ(tx * 4 + j, r)] = s[i][j];
        }
        __syncthreads();

#pragma unroll
        for (int i = 0; i < 4; i++)
#pragma unroll
            for (int j = 0; j < 4; j++) o_acc[i][j] *= corr_i[i];

#pragma unroll
        for (int k = 0; k < 64; k++) {
            int sw = (k >> 2) & 15;
            float4 p = *(float4*)&Ps[k * 64 + ((ty ^ sw) << 2)];
            float4 v = *(float4*)&Vs[k * 64 + tx * 4];
            float pv[4] = {p.x, p.y, p.z, p.w};
            float vv[4] = {v.x, v.y, v.z, v.w};
#pragma unroll
            for (int i = 0; i < 4; i++)
#pragma unroll
                for (int j = 0; j < 4; j++)
                    o_acc[i][j] = fmaf(pv[i], vv[j], o_acc[i][j]);
        }
    }

#pragma unroll
    for (int i = 0; i < 4; i++) {
        int qrow = qt * 64 + ty * 4 + i;
        float inv = 1.0f / l_i[i];
        float4 r;
        r.x = o_acc[i][0] * inv;
        r.y = o_acc[i][1] * inv;
        r.z = o_acc[i][2] * inv;
        r.w = o_acc[i][3] * inv;
        *(float4*)&gO[((size_t)b * NSEQ + qrow) * DMODEL + h * DK + tx * 4] = r;
    }
}

// ---------------------------------------------------------------------------
// Launch
// ---------------------------------------------------------------------------
extern "C" void kernel_launch(void* const* d_in, const int* in_sizes, int n_in,
                              void* d_out, int out_size)
{
    const float* query = (const float*)d_in[0];
    const float* key   = (const float*)d_in[1];
    const float* value = (const float*)d_in[2];
    const int*   mask  = (const int*)  d_in[3];
    const float* Wq    = (const float*)d_in[4];
    const float* bq    = (const float*)d_in[5];
    const float* Wk    = (const float*)d_in[6];
    const float* bk    = (const float*)d_in[7];
    const float* Wv    = (const float*)d_in[8];
    const float* bv    = (const float*)d_in[9];
    const float* Wo    = (const float*)d_in[10];
    const float* bo    = (const float*)d_in[11];

    float *Qp, *Kp, *Vp, *Op;
    cudaGetSymbolAddress((void**)&Qp, g_Q);
    cudaGetSymbolAddress((void**)&Kp, g_K);
    cudaGetSymbolAddress((void**)&Vp, g_V);
    cudaGetSymbolAddress((void**)&Op, g_O);

    cudaFuncSetAttribute(attn_kernel,
                         cudaFuncAttributeMaxDynamicSharedMemorySize, 65536);

    dim3 gp(DMODEL / 128, MROWS / 128);   // (8, 64)
    gemm_mma<true><<<gp, 256>>>(query, Wq, bq, Qp);
    gemm_mma<true><<<gp, 256>>>(key,   Wk, bk, Kp);
    gemm_mma<true><<<gp, 256>>>(value, Wv, bv, Vp);

    attn_kernel<<<dim3(BATCH * NH, NSEQ / 64), 256, 65536>>>(mask, Op);

    gemm_mma<false><<<gp, 256>>>(Op, Wo, bo, (float*)d_out);
}

// round 5
// speedup vs baseline: 1.7980x; 1.2792x over previous
#include <cuda_runtime.h>
#include <cuda_fp16.h>
#include <math.h>
#include <stdint.h>

// Problem constants
#define BATCH   4
#define NSEQ    2048
#define DMODEL  1024
#define NH      16
#define DK      64
#define MROWS   (BATCH * NSEQ)   // 8192

// Scratch (allocation-free rule: __device__ globals)
__device__ float g_Q[BATCH * NH * NSEQ * DK];   // (B,H,N,DK)
__device__ float g_K[BATCH * NH * NSEQ * DK];
__device__ float g_V[BATCH * NH * NSEQ * DK];
__device__ float g_O[BATCH * NSEQ * DMODEL];    // (B,N,D) concat-heads

// ---------------------------------------------------------------------------
// mma.sync helpers (sm_80+ ISA, works on base sm_100 target)
// ---------------------------------------------------------------------------
__device__ __forceinline__ uint32_t smem_u32(const void* p) {
    uint32_t a;
    asm("{ .reg .u64 t; cvta.to.shared.u64 t, %1; cvt.u32.u64 %0, t; }"
        : "=r"(a) : "l"(p));
    return a;
}

__device__ __forceinline__ void ldmx4(uint32_t* r, uint32_t addr) {
    asm volatile("ldmatrix.sync.aligned.m8n8.x4.shared.b16 {%0,%1,%2,%3}, [%4];"
                 : "=r"(r[0]), "=r"(r[1]), "=r"(r[2]), "=r"(r[3]) : "r"(addr));
}
__device__ __forceinline__ void ldmx4t(uint32_t* r, uint32_t addr) {
    asm volatile("ldmatrix.sync.aligned.m8n8.x4.trans.shared.b16 {%0,%1,%2,%3}, [%4];"
                 : "=r"(r[0]), "=r"(r[1]), "=r"(r[2]), "=r"(r[3]) : "r"(addr));
}
__device__ __forceinline__ void mma16816(float* d, const uint32_t* a,
                                         uint32_t b0, uint32_t b1) {
    asm volatile(
        "mma.sync.aligned.m16n8k16.row.col.f32.f16.f16.f32 "
        "{%0,%1,%2,%3}, {%4,%5,%6,%7}, {%8,%9}, {%0,%1,%2,%3};"
        : "+f"(d[0]), "+f"(d[1]), "+f"(d[2]), "+f"(d[3])
        : "r"(a[0]), "r"(a[1]), "r"(a[2]), "r"(a[3]), "r"(b0), "r"(b1));
}

// Split fp32x4 into fp16 hi + fp16 residual, packed as half2 words
__device__ __forceinline__ void split4(float4 v, uint2& hi, uint2& lo) {
    float f[4] = {v.x, v.y, v.z, v.w};
    __half h[4], l[4];
#pragma unroll
    for (int i = 0; i < 4; i++) {
        h[i] = __float2half_rn(f[i]);
        l[i] = __float2half_rn(f[i] - __half2float(h[i]));
    }
    hi.x = (uint32_t)__half_as_ushort(h[0]) | ((uint32_t)__half_as_ushort(h[1]) << 16);
    hi.y = (uint32_t)__half_as_ushort(h[2]) | ((uint32_t)__half_as_ushort(h[3]) << 16);
    lo.x = (uint32_t)__half_as_ushort(l[0]) | ((uint32_t)__half_as_ushort(l[1]) << 16);
    lo.y = (uint32_t)__half_as_ushort(l[2]) | ((uint32_t)__half_as_ushort(l[3]) << 16);
}

// Pack two fp32 into half2 hi + half2 residual words
__device__ __forceinline__ void pack2(float a, float b, uint32_t& hi, uint32_t& lo) {
    __half ha = __float2half_rn(a), hb = __float2half_rn(b);
    __half la = __float2half_rn(a - __half2float(ha));
    __half lb = __float2half_rn(b - __half2float(hb));
    hi = (uint32_t)__half_as_ushort(ha) | ((uint32_t)__half_as_ushort(hb) << 16);
    lo = (uint32_t)__half_as_ushort(la) | ((uint32_t)__half_as_ushort(lb) << 16);
}

// ---------------------------------------------------------------------------
// Fast exp (poly exp2): avoids MUFU EX2 throughput wall
// ---------------------------------------------------------------------------
__device__ __forceinline__ float fexp(float x) {
    float y = x * 1.4426950408889634f;
    y = fmaxf(fminf(y, 126.0f), -126.0f);
    float n = rintf(y);
    float f = y - n;
    float p = 1.33335581e-3f;
    p = fmaf(p, f, 9.61812911e-3f);
    p = fmaf(p, f, 5.55041087e-2f);
    p = fmaf(p, f, 2.40226507e-1f);
    p = fmaf(p, f, 6.93147181e-1f);
    p = fmaf(p, f, 1.0f);
    return __int_as_float((((int)n) + 127) << 23) * p;
}

// ---------------------------------------------------------------------------
// Tensor-core GEMM (validated Round-4): out = X @ W + bias
// ---------------------------------------------------------------------------
#define SA 40
#define SB 136

template <bool SPLIT>
__global__ void __launch_bounds__(256) gemm_mma(
    const float* __restrict__ X, const float* __restrict__ W,
    const float* __restrict__ bias, float* __restrict__ out)
{
    __shared__ __half Ah[128 * SA], Al[128 * SA];
    __shared__ __half Bh[32 * SB],  Bl[32 * SB];

    const int tid = threadIdx.x;
    const int wid = tid >> 5;
    const int lane = tid & 31;
    const int wm = wid & 3;
    const int wn = wid >> 2;
    const int m0 = blockIdx.y * 128;
    const int n0 = blockIdx.x * 128;

    const uint32_t sAh = smem_u32(Ah), sAl = smem_u32(Al);
    const uint32_t sBh = smem_u32(Bh), sBl = smem_u32(Bl);

    float acc[2][8][4];
#pragma unroll
    for (int i = 0; i < 2; i++)
#pragma unroll
        for (int j = 0; j < 8; j++)
#pragma unroll
            for (int q = 0; q < 4; q++) acc[i][j][q] = 0.0f;

    const int lrow = lane & 15;
    const int lcol = (lane >> 4) << 3;

    for (int c = 0; c < 32; ++c) {
        __syncthreads();
        const float* Xc = X + (size_t)m0 * DMODEL + c * 32;
#pragma unroll
        for (int p = 0; p < 4; ++p) {
            int f = tid + p * 256;
            int r = f >> 3;
            int q = f & 7;
            float4 v = *(const float4*)(Xc + (size_t)r * DMODEL + q * 4);
            uint2 hi, lo;
            split4(v, hi, lo);
            *(uint2*)&Ah[r * SA + q * 4] = hi;
            *(uint2*)&Al[r * SA + q * 4] = lo;
        }
        const float* Wc = W + (size_t)(c * 32) * DMODEL + n0;
#pragma unroll
        for (int p = 0; p < 4; ++p) {
            int f = tid + p * 256;
            int k = f >> 5;
            int q = f & 31;
            float4 v = *(const float4*)(Wc + (size_t)k * DMODEL + q * 4);
            uint2 hi, lo;
            split4(v, hi, lo);
            *(uint2*)&Bh[k * SB + q * 4] = hi;
            *(uint2*)&Bl[k * SB + q * 4] = lo;
        }
        __syncthreads();

#pragma unroll
        for (int ks = 0; ks < 2; ++ks) {
            uint32_t ah[2][4], al[2][4];
#pragma unroll
            for (int i = 0; i < 2; i++) {
                uint32_t off = (uint32_t)((wm * 32 + i * 16 + lrow) * SA +
                                          ks * 16 + lcol) * 2;
                ldmx4(ah[i], sAh + off);
                ldmx4(al[i], sAl + off);
            }
#pragma unroll
            for (int j2 = 0; j2 < 4; ++j2) {
                uint32_t bh[4], bl[4];
                uint32_t off = (uint32_t)((ks * 16 + lrow) * SB +
                                          wn * 64 + j2 * 16 + lcol) * 2;
                ldmx4t(bh, sBh + off);
                ldmx4t(bl, sBl + off);
#pragma unroll
                for (int i = 0; i < 2; i++) {
                    mma16816(acc[i][2 * j2],     ah[i], bh[0], bh[1]);
                    mma16816(acc[i][2 * j2 + 1], ah[i], bh[2], bh[3]);
                    mma16816(acc[i][2 * j2],     ah[i], bl[0], bl[1]);
                    mma16816(acc[i][2 * j2 + 1], ah[i], bl[2], bl[3]);
                    mma16816(acc[i][2 * j2],     al[i], bh[0], bh[1]);
                    mma16816(acc[i][2 * j2 + 1], al[i], bh[2], bh[3]);
                }
            }
        }
    }

#pragma unroll
    for (int i = 0; i < 2; i++) {
#pragma unroll
        for (int j = 0; j < 8; j++) {
            int col = n0 + wn * 64 + j * 8 + (lane & 3) * 2;
            float b0 = bias[col], b1 = bias[col + 1];
#pragma unroll
            for (int half = 0; half < 2; half++) {
                int m = m0 + wm * 32 + i * 16 + (lane >> 2) + half * 8;
                float2 r;
                r.x = acc[i][j][half * 2 + 0] + b0;
                r.y = acc[i][j][half * 2 + 1] + b1;
                if (SPLIT) {
                    int bb = m >> 11;
                    int n  = m & 2047;
                    int h  = col >> 6;
                    int dk = col & 63;
                    *(float2*)&out[(((size_t)((bb << 4) + h) * NSEQ + n) * DK) + dk] = r;
                } else {
                    *(float2*)&out[(size_t)m * DMODEL + col] = r;
                }
            }
        }
    }
}

// ---------------------------------------------------------------------------
// Tensor-core flash attention.
// Block = one (b,h) x 128 query rows. 8 warps x 16 rows. Key tiles of 64.
// S = Q K^T: Q,K fragments via non-trans ldmatrix (row-major (seq,dk)).
// Softmax on C-fragments in registers; P repacked C->A layout register-only.
// PV: V via ldmatrix.x4.trans. Split-fp16 3-MMA on both products.
// Smem (36KB): Q staging (2x128x72 halves) overlaid by K/V (4x64x72 halves).
// ---------------------------------------------------------------------------
#define AS 72   // smem stride in halves (144B: rows map to distinct banks)

__global__ void __launch_bounds__(256) attn_mma(
    const int* __restrict__ mask, float* __restrict__ gO)
{
    extern __shared__ __half ash[];
    __half* Kh = ash;                 //  64*72
    __half* Kl = ash + 64 * AS;       //  64*72
    __half* Vh = ash + 128 * AS;      //  64*72
    __half* Vl = ash + 192 * AS;      //  64*72
    __half* Qh = ash;                 // 128*72 (prologue only, overlays K)
    __half* Ql = ash + 128 * AS;      // 128*72 (overlays V)

    const int bh = blockIdx.x;            // 0..63
    const int qt = blockIdx.y;            // 0..15
    const int b  = bh >> 4;
    const int h  = bh & 15;
    const int tid = threadIdx.x;
    const int wid = tid >> 5;
    const int lane = tid & 31;
    const int lrow = lane & 15;
    const int lcol = (lane >> 4) << 3;
    const int qr = lane >> 2;             // fragment row 0..7
    const int qc = (lane & 3) * 2;        // fragment col pair

    const float* Qg = g_Q + ((size_t)bh * NSEQ + qt * 128) * DK;
    const float* Kg = g_K + (size_t)bh * NSEQ * DK;
    const float* Vg = g_V + (size_t)bh * NSEQ * DK;
    const int*   Mg = mask + ((size_t)b * NSEQ + qt * 128) * NSEQ;

    const uint32_t sKh = smem_u32(Kh), sKl = smem_u32(Kl);
    const uint32_t sVh = smem_u32(Vh), sVl = smem_u32(Vl);
    const uint32_t sQh = smem_u32(Qh), sQl = smem_u32(Ql);

    // ---- Prologue: stage Q (split) in smem, hoist fragments to registers ----
#pragma unroll
    for (int p = 0; p < 8; ++p) {
        int f = tid + p * 256;
        int r = f >> 4;            // 0..127
        int d4 = f & 15;
        float4 v = *(const float4*)(Qg + (size_t)r * DK + d4 * 4);
        uint2 hi, lo;
        split4(v, hi, lo);
        *(uint2*)&Qh[r * AS + d4 * 4] = hi;
        *(uint2*)&Ql[r * AS + d4 * 4] = lo;
    }
    __syncthreads();

    uint32_t qfh[4][4], qfl[4][4];
#pragma unroll
    for (int ks = 0; ks < 4; ++ks) {
        uint32_t off = (uint32_t)((wid * 16 + lrow) * AS + ks * 16 + lcol) * 2;
        ldmx4(qfh[ks], sQh + off);
        ldmx4(qfl[ks], sQl + off);
    }

    float oacc[8][4];
#pragma unroll
    for (int j = 0; j < 8; j++)
#pragma unroll
        for (int q = 0; q < 4; q++) oacc[j][q] = 0.0f;
    float m0 = -1e30f, m1 = -1e30f, l0 = 0.0f, l1 = 0.0f;

    const int r0 = wid * 16 + qr;         // local q rows of this thread
    const int r1 = r0 + 8;

    for (int kt = 0; kt < NSEQ; kt += 64) {
        __syncthreads();   // everyone done reading previous K/V (and Q prologue)
        // Load K,V tile: 64 rows x 64 dk, split fp16
#pragma unroll
        for (int p = 0; p < 4; ++p) {
            int f = tid + p * 256;
            int r = f >> 4;        // 0..63
            int d4 = f & 15;
            float4 kv = *(const float4*)(Kg + (size_t)(kt + r) * DK + d4 * 4);
            uint2 hi, lo;
            split4(kv, hi, lo);
            *(uint2*)&Kh[r * AS + d4 * 4] = hi;
            *(uint2*)&Kl[r * AS + d4 * 4] = lo;
            float4 vv = *(const float4*)(Vg + (size_t)(kt + r) * DK + d4 * 4);
            split4(vv, hi, lo);
            *(uint2*)&Vh[r * AS + d4 * 4] = hi;
            *(uint2*)&Vl[r * AS + d4 * 4] = lo;
        }
        __syncthreads();

        // ---- S = Q K^T (split 3-MMA) ----
        float sacc[8][4];
#pragma unroll
        for (int j = 0; j < 8; j++)
#pragma unroll
            for (int q = 0; q < 4; q++) sacc[j][q] = 0.0f;

#pragma unroll
        for (int ks = 0; ks < 4; ++ks) {
#pragma unroll
            for (int g = 0; g < 4; ++g) {
                uint32_t kh[4], kl[4];
                uint32_t off = (uint32_t)((g * 16 + lrow) * AS + ks * 16 + lcol) * 2;
                ldmx4(kh, sKh + off);
                ldmx4(kl, sKl + off);
                mma16816(sacc[2 * g],     qfh[ks], kh[0], kh[2]);
                mma16816(sacc[2 * g],     qfh[ks], kl[0], kl[2]);
                mma16816(sacc[2 * g],     qfl[ks], kh[0], kh[2]);
                mma16816(sacc[2 * g + 1], qfh[ks], kh[1], kh[3]);
                mma16816(sacc[2 * g + 1], qfh[ks], kl[1], kl[3]);
                mma16816(sacc[2 * g + 1], qfl[ks], kh[1], kh[3]);
            }
        }

        // ---- scale + mask ----
#pragma unroll
        for (int j = 0; j < 8; ++j) {
            int col = kt + j * 8 + qc;
            int2 mv0 = *(const int2*)(Mg + (size_t)r0 * NSEQ + col);
            int2 mv1 = *(const int2*)(Mg + (size_t)r1 * NSEQ + col);
            sacc[j][0] = (mv0.x == 0) ? -1e11f : sacc[j][0] * 0.125f;
            sacc[j][1] = (mv0.y == 0) ? -1e11f : sacc[j][1] * 0.125f;
            sacc[j][2] = (mv1.x == 0) ? -1e11f : sacc[j][2] * 0.125f;
            sacc[j][3] = (mv1.y == 0) ? -1e11f : sacc[j][3] * 0.125f;
        }

        // ---- online softmax (rows r0: regs 0,1 ; r1: regs 2,3) ----
        float mx0 = -1e30f, mx1 = -1e30f;
#pragma unroll
        for (int j = 0; j < 8; ++j) {
            mx0 = fmaxf(mx0, fmaxf(sacc[j][0], sacc[j][1]));
            mx1 = fmaxf(mx1, fmaxf(sacc[j][2], sacc[j][3]));
        }
        mx0 = fmaxf(mx0, __shfl_xor_sync(0xffffffffu, mx0, 1));
        mx0 = fmaxf(mx0, __shfl_xor_sync(0xffffffffu, mx0, 2));
        mx1 = fmaxf(mx1, __shfl_xor_sync(0xffffffffu, mx1, 1));
        mx1 = fmaxf(mx1, __shfl_xor_sync(0xffffffffu, mx1, 2));

        float mn0 = fmaxf(m0, mx0), mn1 = fmaxf(m1, mx1);
        float c0 = fexp(m0 - mn0), c1 = fexp(m1 - mn1);
        m0 = mn0; m1 = mn1;

        float rs0 = 0.0f, rs1 = 0.0f;
#pragma unroll
        for (int j = 0; j < 8; ++j) {
            sacc[j][0] = fexp(sacc[j][0] - mn0);
            sacc[j][1] = fexp(sacc[j][1] - mn0);
            sacc[j][2] = fexp(sacc[j][2] - mn1);
            sacc[j][3] = fexp(sacc[j][3] - mn1);
            rs0 += sacc[j][0] + sacc[j][1];
            rs1 += sacc[j][2] + sacc[j][3];
        }
        rs0 += __shfl_xor_sync(0xffffffffu, rs0, 1);
        rs0 += __shfl_xor_sync(0xffffffffu, rs0, 2);
        rs1 += __shfl_xor_sync(0xffffffffu, rs1, 1);
        rs1 += __shfl_xor_sync(0xffffffffu, rs1, 2);
        l0 = l0 * c0 + rs0;
        l1 = l1 * c1 + rs1;

        // ---- O *= corr; O += P V (split 3-MMA) ----
#pragma unroll
        for (int j = 0; j < 8; ++j) {
            oacc[j][0] *= c0; oacc[j][1] *= c0;
            oacc[j][2] *= c1; oacc[j][3] *= c1;
        }

#pragma unroll
        for (int ks = 0; ks < 4; ++ks) {
            // C->A repack: tiles 2ks (k0-7), 2ks+1 (k8-15)
            uint32_t aPh[4], aPl[4];
            pack2(sacc[2 * ks][0],     sacc[2 * ks][1],     aPh[0], aPl[0]);
            pack2(sacc[2 * ks][2],     sacc[2 * ks][3],     aPh[1], aPl[1]);
            pack2(sacc[2 * ks + 1][0], sacc[2 * ks + 1][1], aPh[2], aPl[2]);
            pack2(sacc[2 * ks + 1][2], sacc[2 * ks + 1][3], aPh[3], aPl[3]);
#pragma unroll
            for (int g = 0; g < 4; ++g) {
                uint32_t vh[4], vl[4];
                uint32_t off = (uint32_t)((ks * 16 + lrow) * AS + g * 16 + lcol) * 2;
                ldmx4t(vh, sVh + off);
                ldmx4t(vl, sVl + off);
                mma16816(oacc[2 * g],     aPh, vh[0], vh[1]);
                mma16816(oacc[2 * g],     aPh, vl[0], vl[1]);
                mma16816(oacc[2 * g],     aPl, vh[0], vh[1]);
                mma16816(oacc[2 * g + 1], aPh, vh[2], vh[3]);
                mma16816(oacc[2 * g + 1], aPh, vl[2], vl[3]);
                mma16816(oacc[2 * g + 1], aPl, vh[2], vh[3]);
            }
        }
    }

    // ---- normalize + write concat-heads (B,N,DMODEL) ----
    float inv0 = 1.0f / l0, inv1 = 1.0f / l1;
    int qrow0 = qt * 128 + r0;
    int qrow1 = qt * 128 + r1;
#pragma unroll
    for (int j = 0; j < 8; ++j) {
        int col = h * DK + j * 8 + qc;
        float2 w0, w1;
        w0.x = oacc[j][0] * inv0; w0.y = oacc[j][1] * inv0;
        w1.x = oacc[j][2] * inv1; w1.y = oacc[j][3] * inv1;
        *(float2*)&gO[((size_t)b * NSEQ + qrow0) * DMODEL + col] = w0;
        *(float2*)&gO[((size_t)b * NSEQ + qrow1) * DMODEL + col] = w1;
    }
}

// ---------------------------------------------------------------------------
// Launch
// ---------------------------------------------------------------------------
extern "C" void kernel_launch(void* const* d_in, const int* in_sizes, int n_in,
                              void* d_out, int out_size)
{
    const float* query = (const float*)d_in[0];
    const float* key   = (const float*)d_in[1];
    const float* value = (const float*)d_in[2];
    const int*   mask  = (const int*)  d_in[3];
    const float* Wq    = (const float*)d_in[4];
    const float* bq    = (const float*)d_in[5];
    const float* Wk    = (const float*)d_in[6];
    const float* bk    = (const float*)d_in[7];
    const float* Wv    = (const float*)d_in[8];
    const float* bv    = (const float*)d_in[9];
    const float* Wo    = (const float*)d_in[10];
    const float* bo    = (const float*)d_in[11];

    float *Qp, *Kp, *Vp, *Op;
    cudaGetSymbolAddress((void**)&Qp, g_Q);
    cudaGetSymbolAddress((void**)&Kp, g_K);
    cudaGetSymbolAddress((void**)&Vp, g_V);
    cudaGetSymbolAddress((void**)&Op, g_O);

    dim3 gp(DMODEL / 128, MROWS / 128);   // (8, 64)
    gemm_mma<true><<<gp, 256>>>(query, Wq, bq, Qp);
    gemm_mma<true><<<gp, 256>>>(key,   Wk, bk, Kp);
    gemm_mma<true><<<gp, 256>>>(value, Wv, bv, Vp);

    // 36 KB dynamic smem (<48 KB default cap)
    attn_mma<<<dim3(BATCH * NH, NSEQ / 128), 256, 256 * AS * sizeof(__half)>>>(mask, Op);

    gemm_mma<false><<<gp, 256>>>(Op, Wo, bo, (float*)d_out);
}

// round 7
// speedup vs baseline: 1.9782x; 1.1002x over previous
#include <cuda_runtime.h>
#include <cuda_fp16.h>
#include <math.h>
#include <stdint.h>

// Problem constants
#define BATCH   4
#define NSEQ    2048
#define DMODEL  1024
#define NH      16
#define DK      64
#define MROWS   (BATCH * NSEQ)   // 8192

// Scratch (allocation-free rule: __device__ globals)
__device__ __half g_Qh[BATCH * NH * NSEQ * DK], g_Ql[BATCH * NH * NSEQ * DK];
__device__ __half g_Kh[BATCH * NH * NSEQ * DK], g_Kl[BATCH * NH * NSEQ * DK];
__device__ __half g_Vh[BATCH * NH * NSEQ * DK], g_Vl[BATCH * NH * NSEQ * DK];
__device__ float  g_O[BATCH * NSEQ * DMODEL];    // (B,N,D) concat-heads

// ---------------------------------------------------------------------------
// mma.sync / ldmatrix / cp.async helpers (sm_80+ ISA)
// ---------------------------------------------------------------------------
__device__ __forceinline__ uint32_t smem_u32(const void* p) {
    uint32_t a;
    asm("{ .reg .u64 t; cvta.to.shared.u64 t, %1; cvt.u32.u64 %0, t; }"
        : "=r"(a) : "l"(p));
    return a;
}
__device__ __forceinline__ void ldmx4(uint32_t* r, uint32_t addr) {
    asm volatile("ldmatrix.sync.aligned.m8n8.x4.shared.b16 {%0,%1,%2,%3}, [%4];"
                 : "=r"(r[0]), "=r"(r[1]), "=r"(r[2]), "=r"(r[3]) : "r"(addr));
}
__device__ __forceinline__ void ldmx4t(uint32_t* r, uint32_t addr) {
    asm volatile("ldmatrix.sync.aligned.m8n8.x4.trans.shared.b16 {%0,%1,%2,%3}, [%4];"
                 : "=r"(r[0]), "=r"(r[1]), "=r"(r[2]), "=r"(r[3]) : "r"(addr));
}
__device__ __forceinline__ void mma16816(float* d, const uint32_t* a,
                                         uint32_t b0, uint32_t b1) {
    asm volatile(
        "mma.sync.aligned.m16n8k16.row.col.f32.f16.f16.f32 "
        "{%0,%1,%2,%3}, {%4,%5,%6,%7}, {%8,%9}, {%0,%1,%2,%3};"
        : "+f"(d[0]), "+f"(d[1]), "+f"(d[2]), "+f"(d[3])
        : "r"(a[0]), "r"(a[1]), "r"(a[2]), "r"(a[3]), "r"(b0), "r"(b1));
}
__device__ __forceinline__ void cpa16(uint32_t dst, const void* src) {
    asm volatile("cp.async.cg.shared.global [%0], [%1], 16;"
                 :: "r"(dst), "l"(src) : "memory");
}
#define CPA_COMMIT() asm volatile("cp.async.commit_group;" ::: "memory")
#define CPA_WAIT1()  asm volatile("cp.async.wait_group 1;" ::: "memory")

// Split fp32x4 into fp16 hi + fp16 residual, packed as half2 words
__device__ __forceinline__ void split4(float4 v, uint2& hi, uint2& lo) {
    float f[4] = {v.x, v.y, v.z, v.w};
    __half h[4], l[4];
#pragma unroll
    for (int i = 0; i < 4; i++) {
        h[i] = __float2half_rn(f[i]);
        l[i] = __float2half_rn(f[i] - __half2float(h[i]));
    }
    hi.x = (uint32_t)__half_as_ushort(h[0]) | ((uint32_t)__half_as_ushort(h[1]) << 16);
    hi.y = (uint32_t)__half_as_ushort(h[2]) | ((uint32_t)__half_as_ushort(h[3]) << 16);
    lo.x = (uint32_t)__half_as_ushort(l[0]) | ((uint32_t)__half_as_ushort(l[1]) << 16);
    lo.y = (uint32_t)__half_as_ushort(l[2]) | ((uint32_t)__half_as_ushort(l[3]) << 16);
}
__device__ __forceinline__ void pack2(float a, float b, uint32_t& hi, uint32_t& lo) {
    __half ha = __float2half_rn(a), hb = __float2half_rn(b);
    __half la = __float2half_rn(a - __half2float(ha));
    __half lb = __float2half_rn(b - __half2float(hb));
    hi = (uint32_t)__half_as_ushort(ha) | ((uint32_t)__half_as_ushort(hb) << 16);
    lo = (uint32_t)__half_as_ushort(la) | ((uint32_t)__half_as_ushort(lb) << 16);
}

// Fast exp (poly exp2)
__device__ __forceinline__ float fexp(float x) {
    float y = x * 1.4426950408889634f;
    y = fmaxf(fminf(y, 126.0f), -126.0f);
    float n = rintf(y);
    float f = y - n;
    float p = 1.33335581e-3f;
    p = fmaf(p, f, 9.61812911e-3f);
    p = fmaf(p, f, 5.55041087e-2f);
    p = fmaf(p, f, 2.40226507e-1f);
    p = fmaf(p, f, 6.93147181e-1f);
    p = fmaf(p, f, 1.0f);
    return __int_as_float((((int)n) + 127) << 23) * p;
}

// ---------------------------------------------------------------------------
// Tensor-core GEMM (validated core). HALFOUT: write split fp16 hi/lo to
// outH/outL in head-split (B,H,N,DK) layout; else fp32 plain (M,1024) to outF.
// ---------------------------------------------------------------------------
#define SA 40
#define SB 136

template <bool HALFOUT>
__global__ void __launch_bounds__(256) gemm_mma(
    const float* __restrict__ X, const float* __restrict__ W,
    const float* __restrict__ bias, float* __restrict__ outF,
    __half* __restrict__ outH, __half* __restrict__ outL)
{
    __shared__ __half Ah[128 * SA], Al[128 * SA];
    __shared__ __half Bh[32 * SB],  Bl[32 * SB];

    const int tid = threadIdx.x;
    const int wid = tid >> 5;
    const int lane = tid & 31;
    const int wm = wid & 3;
    const int wn = wid >> 2;
    const int m0 = blockIdx.y * 128;
    const int n0 = blockIdx.x * 128;

    const uint32_t sAh = smem_u32(Ah), sAl = smem_u32(Al);
    const uint32_t sBh = smem_u32(Bh), sBl = smem_u32(Bl);

    float acc[2][8][4];
#pragma unroll
    for (int i = 0; i < 2; i++)
#pragma unroll
        for (int j = 0; j < 8; j++)
#pragma unroll
            for (int q = 0; q < 4; q++) acc[i][j][q] = 0.0f;

    const int lrow = lane & 15;
    const int lcol = (lane >> 4) << 3;

    for (int c = 0; c < 32; ++c) {
        __syncthreads();
        const float* Xc = X + (size_t)m0 * DMODEL + c * 32;
#pragma unroll
        for (int p = 0; p < 4; ++p) {
            int f = tid + p * 256;
            int r = f >> 3;
            int q = f & 7;
            float4 v = *(const float4*)(Xc + (size_t)r * DMODEL + q * 4);
            uint2 hi, lo;
            split4(v, hi, lo);
            *(uint2*)&Ah[r * SA + q * 4] = hi;
            *(uint2*)&Al[r * SA + q * 4] = lo;
        }
        const float* Wc = W + (size_t)(c * 32) * DMODEL + n0;
#pragma unroll
        for (int p = 0; p < 4; ++p) {
            int f = tid + p * 256;
            int k = f >> 5;
            int q = f & 31;
            float4 v = *(const float4*)(Wc + (size_t)k * DMODEL + q * 4);
            uint2 hi, lo;
            split4(v, hi, lo);
            *(uint2*)&Bh[k * SB + q * 4] = hi;
            *(uint2*)&Bl[k * SB + q * 4] = lo;
        }
        __syncthreads();

#pragma unroll
        for (int ks = 0; ks < 2; ++ks) {
            uint32_t ah[2][4], al[2][4];
#pragma unroll
            for (int i = 0; i < 2; i++) {
                uint32_t off = (uint32_t)((wm * 32 + i * 16 + lrow) * SA +
                                          ks * 16 + lcol) * 2;
                ldmx4(ah[i], sAh + off);
                ldmx4(al[i], sAl + off);
            }
#pragma unroll
            for (int j2 = 0; j2 < 4; ++j2) {
                uint32_t bh[4], bl[4];
                uint32_t off = (uint32_t)((ks * 16 + lrow) * SB +
                                          wn * 64 + j2 * 16 + lcol) * 2;
                ldmx4t(bh, sBh + off);
                ldmx4t(bl, sBl + off);
#pragma unroll
                for (int i = 0; i < 2; i++) {
                    mma16816(acc[i][2 * j2],     ah[i], bh[0], bh[1]);
                    mma16816(acc[i][2 * j2 + 1], ah[i], bh[2], bh[3]);
                    mma16816(acc[i][2 * j2],     ah[i], bl[0], bl[1]);
                    mma16816(acc[i][2 * j2 + 1], ah[i], bl[2], bl[3]);
                    mma16816(acc[i][2 * j2],     al[i], bh[0], bh[1]);
                    mma16816(acc[i][2 * j2 + 1], al[i], bh[2], bh[3]);
                }
            }
        }
    }

#pragma unroll
    for (int i = 0; i < 2; i++) {
#pragma unroll
        for (int j = 0; j < 8; j++) {
            int col = n0 + wn * 64 + j * 8 + (lane & 3) * 2;
            float b0 = bias[col], b1 = bias[col + 1];
#pragma unroll
            for (int half = 0; half < 2; half++) {
                int m = m0 + wm * 32 + i * 16 + (lane >> 2) + half * 8;
                float vx = acc[i][j][half * 2 + 0] + b0;
                float vy = acc[i][j][half * 2 + 1] + b1;
                if (HALFOUT) {
                    int bb = m >> 11;
                    int n  = m & 2047;
                    int h  = col >> 6;
                    int dk = col & 63;
                    size_t idx = (((size_t)((bb << 4) + h) * NSEQ + n) * DK) + dk;
                    uint32_t hw, lw;
                    pack2(vx, vy, hw, lw);
                    *(uint32_t*)&outH[idx] = hw;
                    *(uint32_t*)&outL[idx] = lw;
                } else {
                    float2 r2; r2.x = vx; r2.y = vy;
                    *(float2*)&outF[(size_t)m * DMODEL + col] = r2;
                }
            }
        }
    }
}

// ---------------------------------------------------------------------------
// Tensor-core flash attention with cp.async double-buffered K/V.
// Block = one (b,h) x 128 q rows, 8 warps x 16 rows, 64-key tiles.
// K/V arrive pre-split (fp16 hi/lo) from the projection GEMMs: no conversion.
// Smem: 2 stages x (Kh|Kl|Vh|Vl, 64 x 72 halves) = 73728 B. Q overlays stage0.
// ---------------------------------------------------------------------------
#define AS 72
#define TH (64 * AS)               // halves per tensor-half tile (4608)
#define STAGE (4 * TH)             // halves per stage (18432)
#define ATT_SMEM (2 * STAGE * 2)   // bytes (73728)

__global__ void __launch_bounds__(256, 2) attn_mma(
    const int* __restrict__ mask, float* __restrict__ gO)
{
    extern __shared__ __half ash[];

    const int bh = blockIdx.x;            // 0..63
    const int qt = blockIdx.y;            // 0..15
    const int b  = bh >> 4;
    const int h  = bh & 15;
    const int tid = threadIdx.x;
    const int wid = tid >> 5;
    const int lane = tid & 31;
    const int lrow = lane & 15;
    const int lcol = (lane >> 4) << 3;
    const int qr = lane >> 2;
    const int qc = (lane & 3) * 2;

    const __half* Qhg = g_Qh + ((size_t)bh * NSEQ + qt * 128) * DK;
    const __half* Qlg = g_Ql + ((size_t)bh * NSEQ + qt * 128) * DK;
    const __half* Khg = g_Kh + (size_t)bh * NSEQ * DK;
    const __half* Klg = g_Kl + (size_t)bh * NSEQ * DK;
    const __half* Vhg = g_Vh + (size_t)bh * NSEQ * DK;
    const __half* Vlg = g_Vl + (size_t)bh * NSEQ * DK;
    const int*    Mg  = mask + ((size_t)b * NSEQ + qt * 128) * NSEQ;

    const uint32_t sbase = smem_u32(ash);

    // ---- Prologue: stage Q halves in smem (overlay stage0), hoist fragments ----
#pragma unroll
    for (int p = 0; p < 4; ++p) {
        int f = tid + p * 256;           // 0..1023 (8-half chunks)
        int r = f >> 3;                  // 0..127
        int c = f & 7;
        *(uint4*)&ash[r * AS + c * 8] = *(const uint4*)(Qhg + (size_t)r * DK + c * 8);
        *(uint4*)&ash[STAGE + r * AS + c * 8] = *(const uint4*)(Qlg + (size_t)r * DK + c * 8);
    }
    __syncthreads();

    uint32_t qfh[4][4], qfl[4][4];
#pragma unroll
    for (int ks = 0; ks < 4; ++ks) {
        uint32_t off = (uint32_t)((wid * 16 + lrow) * AS + ks * 16 + lcol) * 2;
        ldmx4(qfh[ks], sbase + off);
        ldmx4(qfl[ks], sbase + STAGE * 2 + off);
    }
    __syncthreads();   // Q reads done before cp.async overwrites stage0

    // ---- cp.async stage loader: 2 chunks/thread per tensor-half ----
    auto load_stage = [&](int kt, int sg) {
        uint32_t sb = sbase + (uint32_t)(sg * STAGE) * 2;
#pragma unroll
        for (int p = 0; p < 2; ++p) {
            int f = tid + p * 256;       // 0..511
            int r = f >> 3;              // 0..63
            int c = f & 7;
            uint32_t d = (uint32_t)((r * AS + c * 8) * 2);
            size_t gsrc = (size_t)(kt + r) * DK + c * 8;
            cpa16(sb + d,               Khg + gsrc);
            cpa16(sb + TH * 2 + d,      Klg + gsrc);
            cpa16(sb + TH * 4 + d,      Vhg + gsrc);
            cpa16(sb + TH * 6 + d,      Vlg + gsrc);
        }
    };

    load_stage(0, 0);
    CPA_COMMIT();

    float oacc[8][4];
#pragma unroll
    for (int j = 0; j < 8; j++)
#pragma unroll
        for (int q = 0; q < 4; q++) oacc[j][q] = 0.0f;
    float m0 = -1e30f, m1 = -1e30f, l0 = 0.0f, l1 = 0.0f;

    const int r0 = wid * 16 + qr;
    const int r1 = r0 + 8;

    int it = 0;
    for (int kt = 0; kt < NSEQ; kt += 64, it ^= 1) {
        if (kt + 64 < NSEQ) load_stage(kt + 64, it ^ 1);
        CPA_COMMIT();
        CPA_WAIT1();
        __syncthreads();

        const uint32_t sb  = sbase + (uint32_t)(it * STAGE) * 2;
        const uint32_t sKh = sb, sKl = sb + TH * 2;
        const uint32_t sVh = sb + TH * 4, sVl = sb + TH * 6;

        // ---- S = Q K^T (split 3-MMA) ----
        float sacc[8][4];
#pragma unroll
        for (int j = 0; j < 8; j++)
#pragma unroll
            for (int q = 0; q < 4; q++) sacc[j][q] = 0.0f;

#pragma unroll
        for (int ks = 0; ks < 4; ++ks) {
#pragma unroll
            for (int g = 0; g < 4; ++g) {
                uint32_t kh[4], kl[4];
                uint32_t off = (uint32_t)((g * 16 + lrow) * AS + ks * 16 + lcol) * 2;
                ldmx4(kh, sKh + off);
                ldmx4(kl, sKl + off);
                mma16816(sacc[2 * g],     qfh[ks], kh[0], kh[2]);
                mma16816(sacc[2 * g],     qfh[ks], kl[0], kl[2]);
                mma16816(sacc[2 * g],     qfl[ks], kh[0], kh[2]);
                mma16816(sacc[2 * g + 1], qfh[ks], kh[1], kh[3]);
                mma16816(sacc[2 * g + 1], qfh[ks], kl[1], kl[3]);
                mma16816(sacc[2 * g + 1], qfl[ks], kh[1], kh[3]);
            }
        }

        // ---- scale + mask ----
#pragma unroll
        for (int j = 0; j < 8; ++j) {
            int col = kt + j * 8 + qc;
            int2 mv0 = *(const int2*)(Mg + (size_t)r0 * NSEQ + col);
            int2 mv1 = *(const int2*)(Mg + (size_t)r1 * NSEQ + col);
            sacc[j][0] = (mv0.x == 0) ? -1e11f : sacc[j][0] * 0.125f;
            sacc[j][1] = (mv0.y == 0) ? -1e11f : sacc[j][1] * 0.125f;
            sacc[j][2] = (mv1.x == 0) ? -1e11f : sacc[j][2] * 0.125f;
            sacc[j][3] = (mv1.y == 0) ? -1e11f : sacc[j][3] * 0.125f;
        }

        // ---- online softmax ----
        float mx0 = -1e30f, mx1 = -1e30f;
#pragma unroll
        for (int j = 0; j < 8; ++j) {
            mx0 = fmaxf(mx0, fmaxf(sacc[j][0], sacc[j][1]));
            mx1 = fmaxf(mx1, fmaxf(sacc[j][2], sacc[j][3]));
        }
        mx0 = fmaxf(mx0, __shfl_xor_sync(0xffffffffu, mx0, 1));
        mx0 = fmaxf(mx0, __shfl_xor_sync(0xffffffffu, mx0, 2));
        mx1 = fmaxf(mx1, __shfl_xor_sync(0xffffffffu, mx1, 1));
        mx1 = fmaxf(mx1, __shfl_xor_sync(0xffffffffu, mx1, 2));

        float mn0 = fmaxf(m0, mx0), mn1 = fmaxf(m1, mx1);
        float c0 = fexp(m0 - mn0), c1 = fexp(m1 - mn1);
        m0 = mn0; m1 = mn1;

        float rs0 = 0.0f, rs1 = 0.0f;
#pragma unroll
        for (int j = 0; j < 8; ++j) {
            sacc[j][0] = fexp(sacc[j][0] - mn0);
            sacc[j][1] = fexp(sacc[j][1] - mn0);
            sacc[j][2] = fexp(sacc[j][2] - mn1);
            sacc[j][3] = fexp(sacc[j][3] - mn1);
            rs0 += sacc[j][0] + sacc[j][1];
            rs1 += sacc[j][2] + sacc[j][3];
        }
        rs0 += __shfl_xor_sync(0xffffffffu, rs0, 1);
        rs0 += __shfl_xor_sync(0xffffffffu, rs0, 2);
        rs1 += __shfl_xor_sync(0xffffffffu, rs1, 1);
        rs1 += __shfl_xor_sync(0xffffffffu, rs1, 2);
        l0 = l0 * c0 + rs0;
        l1 = l1 * c1 + rs1;

        // ---- O *= corr; O += P V (split 3-MMA) ----
#pragma unroll
        for (int j = 0; j < 8; ++j) {
            oacc[j][0] *= c0; oacc[j][1] *= c0;
            oacc[j][2] *= c1; oacc[j][3] *= c1;
        }

#pragma unroll
        for (int ks = 0; ks < 4; ++ks) {
            uint32_t aPh[4], aPl[4];
            pack2(sacc[2 * ks][0],     sacc[2 * ks][1],     aPh[0], aPl[0]);
            pack2(sacc[2 * ks][2],     sacc[2 * ks][3],     aPh[1], aPl[1]);
            pack2(sacc[2 * ks + 1][0], sacc[2 * ks + 1][1], aPh[2], aPl[2]);
            pack2(sacc[2 * ks + 1][2], sacc[2 * ks + 1][3], aPh[3], aPl[3]);
#pragma unroll
            for (int g = 0; g < 4; ++g) {
                uint32_t vh[4], vl[4];
                uint32_t off = (uint32_t)((ks * 16 + lrow) * AS + g * 16 + lcol) * 2;
                ldmx4t(vh, sVh + off);
                ldmx4t(vl, sVl + off);
                mma16816(oacc[2 * g],     aPh, vh[0], vh[1]);
                mma16816(oacc[2 * g],     aPh, vl[0], vl[1]);
                mma16816(oacc[2 * g],     aPl, vh[0], vh[1]);
                mma16816(oacc[2 * g + 1], aPh, vh[2], vh[3]);
                mma16816(oacc[2 * g + 1], aPh, vl[2], vl[3]);
                mma16816(oacc[2 * g + 1], aPl, vh[2], vh[3]);
            }
        }
        __syncthreads();   // all warps done with this stage before reuse
    }

    // ---- normalize + write concat-heads (B,N,DMODEL) ----
    float inv0 = 1.0f / l0, inv1 = 1.0f / l1;
    int qrow0 = qt * 128 + r0;
    int qrow1 = qt * 128 + r1;
#pragma unroll
    for (int j = 0; j < 8; ++j) {
        int col = h * DK + j * 8 + qc;
        float2 w0, w1;
        w0.x = oacc[j][0] * inv0; w0.y = oacc[j][1] * inv0;
        w1.x = oacc[j][2] * inv1; w1.y = oacc[j][3] * inv1;
        *(float2*)&gO[((size_t)b * NSEQ + qrow0) * DMODEL + col] = w0;
        *(float2*)&gO[((size_t)b * NSEQ + qrow1) * DMODEL + col] = w1;
    }
}

// ---------------------------------------------------------------------------
// Launch
// ---------------------------------------------------------------------------
extern "C" void kernel_launch(void* const* d_in, const int* in_sizes, int n_in,
                              void* d_out, int out_size)
{
    const float* query = (const float*)d_in[0];
    const float* key   = (const float*)d_in[1];
    const float* value = (const float*)d_in[2];
    const int*   mask  = (const int*)  d_in[3];
    const float* Wq    = (const float*)d_in[4];
    const float* bq    = (const float*)d_in[5];
    const float* Wk    = (const float*)d_in[6];
    const float* bk    = (const float*)d_in[7];
    const float* Wv    = (const float*)d_in[8];
    const float* bv    = (const float*)d_in[9];
    const float* Wo    = (const float*)d_in[10];
    const float* bo    = (const float*)d_in[11];

    __half *Qh, *Ql, *Kh, *Kl, *Vh, *Vl;
    float* Op;
    cudaGetSymbolAddress((void**)&Qh, g_Qh);
    cudaGetSymbolAddress((void**)&Ql, g_Ql);
    cudaGetSymbolAddress((void**)&Kh, g_Kh);
    cudaGetSymbolAddress((void**)&Kl, g_Kl);
    cudaGetSymbolAddress((void**)&Vh, g_Vh);
    cudaGetSymbolAddress((void**)&Vl, g_Vl);
    cudaGetSymbolAddress((void**)&Op, g_O);

    cudaFuncSetAttribute(attn_mma,
                         cudaFuncAttributeMaxDynamicSharedMemorySize, ATT_SMEM);

    dim3 gp(DMODEL / 128, MROWS / 128);   // (8, 64)
    gemm_mma<true><<<gp, 256>>>(query, Wq, bq, nullptr, Qh, Ql);
    gemm_mma<true><<<gp, 256>>>(key,   Wk, bk, nullptr, Kh, Kl);
    gemm_mma<true><<<gp, 256>>>(value, Wv, bv, nullptr, Vh, Vl);

    attn_mma<<<dim3(BATCH * NH, NSEQ / 128), 256, ATT_SMEM>>>(mask, Op);

    gemm_mma<false><<<gp, 256>>>(Op, Wo, bo, (float*)d_out, nullptr, nullptr);
}

// round 10
// speedup vs baseline: 2.4246x; 1.2256x over previous
#include <cuda_runtime.h>
#include <cuda_fp16.h>
#include <math.h>
#include <stdint.h>

// Problem constants
#define BATCH   4
#define NSEQ    2048
#define DMODEL  1024
#define NH      16
#define DK      64
#define MROWS   (BATCH * NSEQ)   // 8192

// Scratch (allocation-free rule: __device__ globals)
__device__ __half g_Qh[BATCH * NH * NSEQ * DK], g_Ql[BATCH * NH * NSEQ * DK];
__device__ __half g_Kh[BATCH * NH * NSEQ * DK], g_Kl[BATCH * NH * NSEQ * DK];
__device__ __half g_Vh[BATCH * NH * NSEQ * DK], g_Vl[BATCH * NH * NSEQ * DK];
__device__ __half g_Xh[MROWS * DMODEL], g_Xl[MROWS * DMODEL];  // X splits; reused as O splits
__device__ __half g_Wh[DMODEL * DMODEL], g_Wl[DMODEL * DMODEL];

// ---------------------------------------------------------------------------
// mma.sync / ldmatrix / cp.async helpers (sm_80+ ISA)
// ---------------------------------------------------------------------------
__device__ __forceinline__ uint32_t smem_u32(const void* p) {
    uint32_t a;
    asm("{ .reg .u64 t; cvta.to.shared.u64 t, %1; cvt.u32.u64 %0, t; }"
        : "=r"(a) : "l"(p));
    return a;
}
__device__ __forceinline__ void ldmx4(uint32_t* r, uint32_t addr) {
    asm volatile("ldmatrix.sync.aligned.m8n8.x4.shared.b16 {%0,%1,%2,%3}, [%4];"
                 : "=r"(r[0]), "=r"(r[1]), "=r"(r[2]), "=r"(r[3]) : "r"(addr));
}
__device__ __forceinline__ void ldmx4t(uint32_t* r, uint32_t addr) {
    asm volatile("ldmatrix.sync.aligned.m8n8.x4.trans.shared.b16 {%0,%1,%2,%3}, [%4];"
                 : "=r"(r[0]), "=r"(r[1]), "=r"(r[2]), "=r"(r[3]) : "r"(addr));
}
__device__ __forceinline__ void mma16816(float* d, const uint32_t* a,
                                         uint32_t b0, uint32_t b1) {
    asm volatile(
        "mma.sync.aligned.m16n8k16.row.col.f32.f16.f16.f32 "
        "{%0,%1,%2,%3}, {%4,%5,%6,%7}, {%8,%9}, {%0,%1,%2,%3};"
        : "+f"(d[0]), "+f"(d[1]), "+f"(d[2]), "+f"(d[3])
        : "r"(a[0]), "r"(a[1]), "r"(a[2]), "r"(a[3]), "r"(b0), "r"(b1));
}
__device__ __forceinline__ void cpa16(uint32_t dst, const void* src) {
    asm volatile("cp.async.cg.shared.global [%0], [%1], 16;"
                 :: "r"(dst), "l"(src) : "memory");
}
#define CPA_COMMIT() asm volatile("cp.async.commit_group;" ::: "memory")
#define CPA_WAIT1()  asm volatile("cp.async.wait_group 1;" ::: "memory")

// Split fp32x4 into fp16 hi + fp16 residual, packed as half2 words
__device__ __forceinline__ void split4(float4 v, uint2& hi, uint2& lo) {
    float f[4] = {v.x, v.y, v.z, v.w};
    __half h[4], l[4];
#pragma unroll
    for (int i = 0; i < 4; i++) {
        h[i] = __float2half_rn(f[i]);
        l[i] = __float2half_rn(f[i] - __half2float(h[i]));
    }
    hi.x = (uint32_t)__half_as_ushort(h[0]) | ((uint32_t)__half_as_ushort(h[1]) << 16);
    hi.y = (uint32_t)__half_as_ushort(h[2]) | ((uint32_t)__half_as_ushort(h[3]) << 16);
    lo.x = (uint32_t)__half_as_ushort(l[0]) | ((uint32_t)__half_as_ushort(l[1]) << 16);
    lo.y = (uint32_t)__half_as_ushort(l[2]) | ((uint32_t)__half_as_ushort(l[3]) << 16);
}
__device__ __forceinline__ void pack2(float a, float b, uint32_t& hi, uint32_t& lo) {
    __half ha = __float2half_rn(a), hb = __float2half_rn(b);
    __half la = __float2half_rn(a - __half2float(ha));
    __half lb = __float2half_rn(b - __half2float(hb));
    hi = (uint32_t)__half_as_ushort(ha) | ((uint32_t)__half_as_ushort(hb) << 16);
    lo = (uint32_t)__half_as_ushort(la) | ((uint32_t)__half_as_ushort(lb) << 16);
}

// Fast exp (poly exp2)
__device__ __forceinline__ float fexp(float x) {
    float y = x * 1.4426950408889634f;
    y = fmaxf(fminf(y, 126.0f), -126.0f);
    float n = rintf(y);
    float f = y - n;
    float p = 1.33335581e-3f;
    p = fmaf(p, f, 9.61812911e-3f);
    p = fmaf(p, f, 5.55041087e-2f);
    p = fmaf(p, f, 2.40226507e-1f);
    p = fmaf(p, f, 6.93147181e-1f);
    p = fmaf(p, f, 1.0f);
    return __int_as_float((((int)n) + 127) << 23) * p;
}

// ---------------------------------------------------------------------------
// One-shot fp32 -> split fp16 hi/lo converter (grid-stride, float4-wide)
// ---------------------------------------------------------------------------
__global__ void __launch_bounds__(256) split_kernel(
    const float* __restrict__ in, __half* __restrict__ oh,
    __half* __restrict__ ol, int n4)
{
    for (int i = blockIdx.x * blockDim.x + threadIdx.x; i < n4;
         i += gridDim.x * blockDim.x) {
        float4 v = ((const float4*)in)[i];
        uint2 hi, lo;
        split4(v, hi, lo);
        ((uint2*)oh)[i] = hi;
        ((uint2*)ol)[i] = lo;
    }
}

// ---------------------------------------------------------------------------
// Pre-split tensor-core GEMM with cp.async double buffering.
// out = A(8192x1024) @ B(1024x1024) + bias; A,B given as fp16 hi/lo pairs.
// CTA 128x128, BK=32, 8 warps (4m x 2n). Split 3-MMA, fp32 accum.
// Smem: 2 stages x (Ah|Al 128x40 + Bh|Bl 32x136 halves) = 75776 B.
// ---------------------------------------------------------------------------
#define GA 40
#define GB 136
#define ASTG (128 * GA)              // 5120 halves
#define BSTG (32 * GB)               // 4352 halves
#define GSTG (2 * ASTG + 2 * BSTG)   // 18944 halves per stage
#define GEMM_SMEM (2 * GSTG * 2)     // 75776 bytes

template <bool HALFOUT>
__global__ void __launch_bounds__(256, 2) gemm_ps(
    const __half* __restrict__ Agh, const __half* __restrict__ Agl,
    const __half* __restrict__ Bgh, const __half* __restrict__ Bgl,
    const float* __restrict__ bias, float* __restrict__ outF,
    __half* __restrict__ outH, __half* __restrict__ outL)
{
    extern __shared__ __half gsh[];
    const uint32_t sbase = smem_u32(gsh);

    const int tid = threadIdx.x;
    const int wid = tid >> 5;
    const int lane = tid & 31;
    const int wm = wid & 3;
    const int wn = wid >> 2;
    const int m0 = blockIdx.y * 128;
    const int n0 = blockIdx.x * 128;

    const int lrow = lane & 15;
    const int lcol = (lane >> 4) << 3;

    auto load_stage = [&](int c, int s) {
        uint32_t sb = sbase + (uint32_t)(s * GSTG) * 2;
        // A: 128 rows x 32 halves = 512 chunks of 8 halves
#pragma unroll
        for (int p = 0; p < 2; ++p) {
            int f = tid + p * 256;
            int r = f >> 2;          // 0..127
            int q = f & 3;           // 0..3
            uint32_t d = (uint32_t)((r * GA + q * 8) * 2);
            size_t gsrc = (size_t)(m0 + r) * DMODEL + c * 32 + q * 8;
            cpa16(sb + d,            Agh + gsrc);
            cpa16(sb + ASTG * 2 + d, Agl + gsrc);
        }
        // B: 32 rows x 128 halves = 512 chunks
#pragma unroll
        for (int p = 0; p < 2; ++p) {
            int f = tid + p * 256;
            int r = f >> 4;          // 0..31
            int q = f & 15;          // 0..15
            uint32_t d = (uint32_t)((r * GB + q * 8) * 2);
            size_t gsrc = (size_t)(c * 32 + r) * DMODEL + n0 + q * 8;
            cpa16(sb + 2 * ASTG * 2 + d,            Bgh + gsrc);
            cpa16(sb + (2 * ASTG + BSTG) * 2 + d,   Bgl + gsrc);
        }
    };

    float acc[2][8][4];
#pragma unroll
    for (int i = 0; i < 2; i++)
#pragma unroll
        for (int j = 0; j < 8; j++)
#pragma unroll
            for (int q = 0; q < 4; q++) acc[i][j][q] = 0.0f;

    load_stage(0, 0);
    CPA_COMMIT();

    for (int c = 0; c < 32; ++c) {
        if (c + 1 < 32) load_stage(c + 1, (c + 1) & 1);
        CPA_COMMIT();
        CPA_WAIT1();
        __syncthreads();

        const uint32_t sb  = sbase + (uint32_t)((c & 1) * GSTG) * 2;
        const uint32_t sAh = sb, sAl = sb + ASTG * 2;
        const uint32_t sBh = sb + 2 * ASTG * 2, sBl = sBh + BSTG * 2;

#pragma unroll
        for (int ks = 0; ks < 2; ++ks) {
            uint32_t ah[2][4], al[2][4];
#pragma unroll
            for (int i = 0; i < 2; i++) {
                uint32_t off = (uint32_t)((wm * 32 + i * 16 + lrow) * GA +
                                          ks * 16 + lcol) * 2;
                ldmx4(ah[i], sAh + off);
                ldmx4(al[i], sAl + off);
            }
#pragma unroll
            for (int j2 = 0; j2 < 4; ++j2) {
                uint32_t bh[4], bl[4];
                uint32_t off = (uint32_t)((ks * 16 + lrow) * GB +
                                          wn * 64 + j2 * 16 + lcol) * 2;
                ldmx4t(bh, sBh + off);
                ldmx4t(bl, sBl + off);
#pragma unroll
                for (int i = 0; i < 2; i++) {
                    mma16816(acc[i][2 * j2],     ah[i], bh[0], bh[1]);
                    mma16816(acc[i][2 * j2 + 1], ah[i], bh[2], bh[3]);
                    mma16816(acc[i][2 * j2],     ah[i], bl[0], bl[1]);
                    mma16816(acc[i][2 * j2 + 1], ah[i], bl[2], bl[3]);
                    mma16816(acc[i][2 * j2],     al[i], bh[0], bh[1]);
                    mma16816(acc[i][2 * j2 + 1], al[i], bh[2], bh[3]);
                }
            }
        }
        __syncthreads();   // all warps done with this stage before next prefetch
    }

#pragma unroll
    for (int i = 0; i < 2; i++) {
#pragma unroll
        for (int j = 0; j < 8; j++) {
            int col = n0 + wn * 64 + j * 8 + (lane & 3) * 2;
            float b0 = bias[col], b1 = bias[col + 1];
#pragma unroll
            for (int half = 0; half < 2; half++) {
                int m = m0 + wm * 32 + i * 16 + (lane >> 2) + half * 8;
                float vx = acc[i][j][half * 2 + 0] + b0;
                float vy = acc[i][j][half * 2 + 1] + b1;
                if (HALFOUT) {
                    int bb = m >> 11;
                    int n  = m & 2047;
                    int h  = col >> 6;
                    int dk = col & 63;
                    size_t idx = (((size_t)((bb << 4) + h) * NSEQ + n) * DK) + dk;
                    uint32_t hw, lw;
                    pack2(vx, vy, hw, lw);
                    *(uint32_t*)&outH[idx] = hw;
                    *(uint32_t*)&outL[idx] = lw;
                } else {
                    float2 r2; r2.x = vx; r2.y = vy;
                    *(float2*)&outF[(size_t)m * DMODEL + col] = r2;
                }
            }
        }
    }
}

// ---------------------------------------------------------------------------
// Tensor-core flash attention with cp.async double-buffered K/V (validated).
// Epilogue writes O as split fp16 hi/lo in (M,1024) layout for the O-proj.
// ---------------------------------------------------------------------------
#define AS 72
#define TH (64 * AS)               // halves per tensor-half tile (4608)
#define STAGE (4 * TH)             // halves per stage (18432)
#define ATT_SMEM (2 * STAGE * 2)   // bytes (73728)

__global__ void __launch_bounds__(256, 2) attn_mma(
    const int* __restrict__ mask,
    __half* __restrict__ gOh, __half* __restrict__ gOl)
{
    extern __shared__ __half ash[];

    const int bh = blockIdx.x;            // 0..63
    const int qt = blockIdx.y;            // 0..15
    const int b  = bh >> 4;
    const int h  = bh & 15;
    const int tid = threadIdx.x;
    const int wid = tid >> 5;
    const int lane = tid & 31;
    const int lrow = lane & 15;
    const int lcol = (lane >> 4) << 3;
    const int qr = lane >> 2;
    const int qc = (lane & 3) * 2;

    const __half* Qhg = g_Qh + ((size_t)bh * NSEQ + qt * 128) * DK;
    const __half* Qlg = g_Ql + ((size_t)bh * NSEQ + qt * 128) * DK;
    const __half* Khg = g_Kh + (size_t)bh * NSEQ * DK;
    const __half* Klg = g_Kl + (size_t)bh * NSEQ * DK;
    const __half* Vhg = g_Vh + (size_t)bh * NSEQ * DK;
    const __half* Vlg = g_Vl + (size_t)bh * NSEQ * DK;
    const int*    Mg  = mask + ((size_t)b * NSEQ + qt * 128) * NSEQ;

    const uint32_t sbase = smem_u32(ash);

    // ---- Prologue: stage Q halves (overlay stage0), hoist fragments ----
#pragma unroll
    for (int p = 0; p < 4; ++p) {
        int f = tid + p * 256;
        int r = f >> 3;
        int c = f & 7;
        *(uint4*)&ash[r * AS + c * 8] = *(const uint4*)(Qhg + (size_t)r * DK + c * 8);
        *(uint4*)&ash[STAGE + r * AS + c * 8] = *(const uint4*)(Qlg + (size_t)r * DK + c * 8);
    }
    __syncthreads();

    uint32_t qfh[4][4], qfl[4][4];
#pragma unroll
    for (int ks = 0; ks < 4; ++ks) {
        uint32_t off = (uint32_t)((wid * 16 + lrow) * AS + ks * 16 + lcol) * 2;
        ldmx4(qfh[ks], sbase + off);
        ldmx4(qfl[ks], sbase + STAGE * 2 + off);
    }
    __syncthreads();

    auto load_stage = [&](int kt, int sg) {
        uint32_t sb = sbase + (uint32_t)(sg * STAGE) * 2;
#pragma unroll
        for (int p = 0; p < 2; ++p) {
            int f = tid + p * 256;
            int r = f >> 3;
            int c = f & 7;
            uint32_t d = (uint32_t)((r * AS + c * 8) * 2);
            size_t gsrc = (size_t)(kt + r) * DK + c * 8;
            cpa16(sb + d,          Khg + gsrc);
            cpa16(sb + TH * 2 + d, Klg + gsrc);
            cpa16(sb + TH * 4 + d, Vhg + gsrc);
            cpa16(sb + TH * 6 + d, Vlg + gsrc);
        }
    };

    load_stage(0, 0);
    CPA_COMMIT();

    float oacc[8][4];
#pragma unroll
    for (int j = 0; j < 8; j++)
#pragma unroll
        for (int q = 0; q < 4; q++) oacc[j][q] = 0.0f;
    float m0 = -1e30f, m1 = -1e30f, l0 = 0.0f, l1 = 0.0f;

    const int r0 = wid * 16 + qr;
    const int r1 = r0 + 8;

    int it = 0;
    for (int kt = 0; kt < NSEQ; kt += 64, it ^= 1) {
        if (kt + 64 < NSEQ) load_stage(kt + 64, it ^ 1);
        CPA_COMMIT();
        CPA_WAIT1();
        __syncthreads();

        const uint32_t sb  = sbase + (uint32_t)(it * STAGE) * 2;
        const uint32_t sKh = sb, sKl = sb + TH * 2;
        const uint32_t sVh = sb + TH * 4, sVl = sb + TH * 6;

        float sacc[8][4];
#pragma unroll
        for (int j = 0; j < 8; j++)
#pragma unroll
            for (int q = 0; q < 4; q++) sacc[j][q] = 0.0f;

#pragma unroll
        for (int ks = 0; ks < 4; ++ks) {
#pragma unroll
            for (int g = 0; g < 4; ++g) {
                uint32_t kh[4], kl[4];
                uint32_t off = (uint32_t)((g * 16 + lrow) * AS + ks * 16 + lcol) * 2;
                ldmx4(kh, sKh + off);
                ldmx4(kl, sKl + off);
                mma16816(sacc[2 * g],     qfh[ks], kh[0], kh[2]);
                mma16816(sacc[2 * g],     qfh[ks], kl[0], kl[2]);
                mma16816(sacc[2 * g],     qfl[ks], kh[0], kh[2]);
                mma16816(sacc[2 * g + 1], qfh[ks], kh[1], kh[3]);
                mma16816(sacc[2 * g + 1], qfh[ks], kl[1], kl[3]);
                mma16816(sacc[2 * g + 1], qfl[ks], kh[1], kh[3]);
            }
        }

#pragma unroll
        for (int j = 0; j < 8; ++j) {
            int col = kt + j * 8 + qc;
            int2 mv0 = *(const int2*)(Mg + (size_t)r0 * NSEQ + col);
            int2 mv1 = *(const int2*)(Mg + (size_t)r1 * NSEQ + col);
            sacc[j][0] = (mv0.x == 0) ? -1e11f : sacc[j][0] * 0.125f;
            sacc[j][1] = (mv0.y == 0) ? -1e11f : sacc[j][1] * 0.125f;
            sacc[j][2] = (mv1.x == 0) ? -1e11f : sacc[j][2] * 0.125f;
            sacc[j][3] = (mv1.y == 0) ? -1e11f : sacc[j][3] * 0.125f;
        }

        float mx0 = -1e30f, mx1 = -1e30f;
#pragma unroll
        for (int j = 0; j < 8; ++j) {
            mx0 = fmaxf(mx0, fmaxf(sacc[j][0], sacc[j][1]));
            mx1 = fmaxf(mx1, fmaxf(sacc[j][2], sacc[j][3]));
        }
        mx0 = fmaxf(mx0, __shfl_xor_sync(0xffffffffu, mx0, 1));
        mx0 = fmaxf(mx0, __shfl_xor_sync(0xffffffffu, mx0, 2));
        mx1 = fmaxf(mx1, __shfl_xor_sync(0xffffffffu, mx1, 1));
        mx1 = fmaxf(mx1, __shfl_xor_sync(0xffffffffu, mx1, 2));

        float mn0 = fmaxf(m0, mx0), mn1 = fmaxf(m1, mx1);
        float c0 = fexp(m0 - mn0), c1 = fexp(m1 - mn1);
        m0 = mn0; m1 = mn1;

        float rs0 = 0.0f, rs1 = 0.0f;
#pragma unroll
        for (int j = 0; j < 8; ++j) {
            sacc[j][0] = fexp(sacc[j][0] - mn0);
            sacc[j][1] = fexp(sacc[j][1] - mn0);
            sacc[j][2] = fexp(sacc[j][2] - mn1);
            sacc[j][3] = fexp(sacc[j][3] - mn1);
            rs0 += sacc[j][0] + sacc[j][1];
            rs1 += sacc[j][2] + sacc[j][3];
        }
        rs0 += __shfl_xor_sync(0xffffffffu, rs0, 1);
        rs0 += __shfl_xor_sync(0xffffffffu, rs0, 2);
        rs1 += __shfl_xor_sync(0xffffffffu, rs1, 1);
        rs1 += __shfl_xor_sync(0xffffffffu, rs1, 2);
        l0 = l0 * c0 + rs0;
        l1 = l1 * c1 + rs1;

#pragma unroll
        for (int j = 0; j < 8; ++j) {
            oacc[j][0] *= c0; oacc[j][1] *= c0;
            oacc[j][2] *= c1; oacc[j][3] *= c1;
        }

#pragma unroll
        for (int ks = 0; ks < 4; ++ks) {
            uint32_t aPh[4], aPl[4];
            pack2(sacc[2 * ks][0],     sacc[2 * ks][1],     aPh[0], aPl[0]);
            pack2(sacc[2 * ks][2],     sacc[2 * ks][3],     aPh[1], aPl[1]);
            pack2(sacc[2 * ks + 1][0], sacc[2 * ks + 1][1], aPh[2], aPl[2]);
            pack2(sacc[2 * ks + 1][2], sacc[2 * ks + 1][3], aPh[3], aPl[3]);
#pragma unroll
            for (int g = 0; g < 4; ++g) {
                uint32_t vh[4], vl[4];
                uint32_t off = (uint32_t)((ks * 16 + lrow) * AS + g * 16 + lcol) * 2;
                ldmx4t(vh, sVh + off);
                ldmx4t(vl, sVl + off);
                mma16816(oacc[2 * g],     aPh, vh[0], vh[1]);
                mma16816(oacc[2 * g],     aPh, vl[0], vl[1]);
                mma16816(oacc[2 * g],     aPl, vh[0], vh[1]);
                mma16816(oacc[2 * g + 1], aPh, vh[2], vh[3]);
                mma16816(oacc[2 * g + 1], aPh, vl[2], vl[3]);
                mma16816(oacc[2 * g + 1], aPl, vh[2], vh[3]);
            }
        }
        __syncthreads();
    }

    // ---- normalize + write O as split halves, (M,1024) concat-heads ----
    float inv0 = 1.0f / l0, inv1 = 1.0f / l1;
    int qrow0 = qt * 128 + r0;
    int qrow1 = qt * 128 + r1;
#pragma unroll
    for (int j = 0; j < 8; ++j) {
        int col = h * DK + j * 8 + qc;
        size_t i0 = ((size_t)b * NSEQ + qrow0) * DMODEL + col;
        size_t i1 = ((size_t)b * NSEQ + qrow1) * DMODEL + col;
        uint32_t hw, lw;
        pack2(oacc[j][0] * inv0, oacc[j][1] * inv0, hw, lw);
        *(uint32_t*)&gOh[i0] = hw;
        *(uint32_t*)&gOl[i0] = lw;
        pack2(oacc[j][2] * inv1, oacc[j][3] * inv1, hw, lw);
        *(uint32_t*)&gOh[i1] = hw;
        *(uint32_t*)&gOl[i1] = lw;
    }
}

// ---------------------------------------------------------------------------
// Launch
// ---------------------------------------------------------------------------
extern "C" void kernel_launch(void* const* d_in, const int* in_sizes, int n_in,
                              void* d_out, int out_size)
{
    const float* query = (const float*)d_in[0];
    const float* key   = (const float*)d_in[1];
    const float* value = (const float*)d_in[2];
    const int*   mask  = (const int*)  d_in[3];
    const float* Wq    = (const float*)d_in[4];
    const float* bq    = (const float*)d_in[5];
    const float* Wk    = (const float*)d_in[6];
    const float* bk    = (const float*)d_in[7];
    const float* Wv    = (const float*)d_in[8];
    const float* bv    = (const float*)d_in[9];
    const float* Wo    = (const float*)d_in[10];
    const float* bo    = (const float*)d_in[11];

    __half *Qh, *Ql, *Kh, *Kl, *Vh, *Vl, *Xh, *Xl, *Wh, *Wl;
    cudaGetSymbolAddress((void**)&Qh, g_Qh);
    cudaGetSymbolAddress((void**)&Ql, g_Ql);
    cudaGetSymbolAddress((void**)&Kh, g_Kh);
    cudaGetSymbolAddress((void**)&Kl, g_Kl);
    cudaGetSymbolAddress((void**)&Vh, g_Vh);
    cudaGetSymbolAddress((void**)&Vl, g_Vl);
    cudaGetSymbolAddress((void**)&Xh, g_Xh);
    cudaGetSymbolAddress((void**)&Xl, g_Xl);
    cudaGetSymbolAddress((void**)&Wh, g_Wh);
    cudaGetSymbolAddress((void**)&Wl, g_Wl);

    cudaFuncSetAttribute(attn_mma,
                         cudaFuncAttributeMaxDynamicSharedMemorySize, ATT_SMEM);
    cudaFuncSetAttribute(gemm_ps<true>,
                         cudaFuncAttributeMaxDynamicSharedMemorySize, GEMM_SMEM);
    cudaFuncSetAttribute(gemm_ps<false>,
                         cudaFuncAttributeMaxDynamicSharedMemorySize, GEMM_SMEM);

    const int nX4 = MROWS * DMODEL / 4;     // 2M
    const int nW4 = DMODEL * DMODEL / 4;    // 256K
    dim3 gp(DMODEL / 128, MROWS / 128);     // (8, 64)

    // Q projection
    split_kernel<<<1024, 256>>>(query, Xh, Xl, nX4);
    split_kernel<<<1024, 256>>>(Wq, Wh, Wl, nW4);
    gemm_ps<true><<<gp, 256, GEMM_SMEM>>>(Xh, Xl, Wh, Wl, bq, nullptr, Qh, Ql);
    // K projection
    split_kernel<<<1024, 256>>>(key, Xh, Xl, nX4);
    split_kernel<<<1024, 256>>>(Wk, Wh, Wl, nW4);
    gemm_ps<true><<<gp, 256, GEMM_SMEM>>>(Xh, Xl, Wh, Wl, bk, nullptr, Kh, Kl);
    // V projection
    split_kernel<<<1024, 256>>>(value, Xh, Xl, nX4);
    split_kernel<<<1024, 256>>>(Wv, Wh, Wl, nW4);
    gemm_ps<true><<<gp, 256, GEMM_SMEM>>>(Xh, Xl, Wh, Wl, bv, nullptr, Vh, Vl);

    // Attention (writes O splits into Xh/Xl, reused)
    attn_mma<<<dim3(BATCH * NH, NSEQ / 128), 256, ATT_SMEM>>>(mask, Xh, Xl);

    // O projection
    split_kernel<<<1024, 256>>>(Wo, Wh, Wl, nW4);
    gemm_ps<false><<<gp, 256, GEMM_SMEM>>>(Xh, Xl, Wh, Wl, bo,
                                           (float*)d_out, nullptr, nullptr);
}